// round 9
// baseline (speedup 1.0000x reference)
#include <cuda_runtime.h>
#include <cuda_bf16.h>
#include <cstdint>
#include <math.h>

// ---------------- problem constants ----------------
#define N0 120000
#define N1 24000
#define N2 6000
#define D  256
#define H1 8
#define C1 64
#define HC1 (H1*C1)     // 512
#define H2 8
#define C2 256
#define HC2 (H2*C2)     // 2048
#define E1MAX 384000
#define E2MAX 96000
#define NEG_SLOPE 0.2f

#define KS1 (2*D)       // 512  layer1 A/B storage K (hi|lo)
#define KS2 (2*HC1)     // 1024 layer2

// ---------------- scratch (static device globals; no allocation) ----------------
__device__ float g_h1[(size_t)N0 * HC1];     // 245.8 MB
__device__ float g_h2[(size_t)N1 * HC2];     // 196.6 MB
__device__ float g_as1[(size_t)N0 * H1];
__device__ float g_ad1[(size_t)N1 * H1];
__device__ float g_as2[(size_t)N1 * H2];
__device__ float g_ad2[(size_t)N2 * H2];
__device__ int g_deg1[N1];
__device__ int g_rp1[N1 + 1];
__device__ int g_cur1[N1];
__device__ int g_col1[E1MAX];
__device__ int g_deg2[N2];
__device__ int g_rp2[N2 + 1];
__device__ int g_cur2[N2];
__device__ int g_col2[E2MAX];
// split-precision bf16 operands [hi|lo]
__device__ __nv_bfloat16 g_a1p[(size_t)N0 * KS1];   // 122.9 MB
__device__ __nv_bfloat16 g_b1p[(size_t)HC1 * KS1];  //  0.5 MB
__device__ __nv_bfloat16 g_a2p[(size_t)N1 * KS2];   //  49.2 MB
__device__ __nv_bfloat16 g_b2p[(size_t)HC2 * KS2];  //  4.2 MB

// ================= PTX helpers =================
__device__ __forceinline__ uint32_t smem_u32(const void* p) {
    uint32_t a;
    asm("{ .reg .u64 t; cvta.to.shared.u64 t, %1; cvt.u32.u64 %0, t; }" : "=r"(a) : "l"(p));
    return a;
}
#define CP_ASYNC16(sp, gp) \
    asm volatile("cp.async.cg.shared.global [%0], [%1], 16;" :: "r"(sp), "l"(gp) : "memory")
#define CP_COMMIT() asm volatile("cp.async.commit_group;" ::: "memory")
#define CP_WAIT(n)  asm volatile("cp.async.wait_group %0;" :: "n"(n) : "memory")
#define LDMX4(r, addr) \
    asm volatile("ldmatrix.sync.aligned.m8n8.x4.shared.b16 {%0,%1,%2,%3}, [%4];" \
        : "=r"((r)[0]), "=r"((r)[1]), "=r"((r)[2]), "=r"((r)[3]) : "r"(addr))
#define MMA16816(d, a, b0v, b1v) \
    asm volatile("mma.sync.aligned.m16n8k16.row.col.f32.bf16.bf16.f32 " \
        "{%0,%1,%2,%3}, {%4,%5,%6,%7}, {%8,%9}, {%0,%1,%2,%3};" \
        : "+f"((d)[0]), "+f"((d)[1]), "+f"((d)[2]), "+f"((d)[3]) \
        : "r"((a)[0]), "r"((a)[1]), "r"((a)[2]), "r"((a)[3]), "r"(b0v), "r"(b1v))

// ================= bf16 mma.sync GEMM, superchunk 3-term split, fused scores ====
// A stored [M, 2K] = [hi|lo], B stored [Nfull, 2K] = [hi|lo].
// Superchunk sc = one 64-wide K column with ALL FOUR tiles resident
// {A_hi, A_lo, B_hi, B_lo} (4 x 16KB = 64KB/stage). All 3 split terms
// (hh, lh, hl) computed against one residency -> 34% less smem traffic/MAC.
// 3 stages x 64KB = 192KB smem -> 1 CTA (256 thr) per SM.
#define TSTAGE 65536
#define SMEM_GEMM (3 * TSTAGE)

__device__ __forceinline__ void gemm_load_super(
    const __nv_bfloat16* __restrict__ A, const __nv_bfloat16* __restrict__ B,
    int M, int Kst, int bm, int bn, int sc, uint32_t stbase, int tid)
{
    const int K = Kst >> 1;
    const int coff = sc << 6;
    const int r0 = tid >> 3;
    const int kseg = tid & 7;
    const uint32_t kb = (uint32_t)(kseg * 16);
#pragma unroll
    for (int i = 0; i < 4; i++) {
        int row = r0 + i * 32;
        int grow = bm + row; if (grow >= M) grow = M - 1;
        const __nv_bfloat16* ga = A + (size_t)grow * Kst + coff + kseg * 8;
        uint32_t sp = stbase + (uint32_t)(row * 128) + (kb ^ (uint32_t)((row & 7) << 4));
        CP_ASYNC16(sp, (const void*)ga);                 // A_hi
        CP_ASYNC16(sp + 16384, (const void*)(ga + K));   // A_lo
    }
#pragma unroll
    for (int i = 0; i < 4; i++) {
        int row = r0 + i * 32;
        const __nv_bfloat16* gb = B + (size_t)(bn + row) * Kst + coff + kseg * 8;
        uint32_t sp = stbase + 32768 + (uint32_t)(row * 128) + (kb ^ (uint32_t)((row & 7) << 4));
        CP_ASYNC16(sp, (const void*)gb);                 // B_hi
        CP_ASYNC16(sp + 16384, (const void*)(gb + K));   // B_lo
    }
}

__global__ __launch_bounds__(256, 1) void gemm_mma(
    const __nv_bfloat16* __restrict__ A, const __nv_bfloat16* __restrict__ B,
    float* __restrict__ C, int M, int Nfull, int Kst,
    const float* __restrict__ attS, const float* __restrict__ attD,
    float* __restrict__ aS, float* __restrict__ aD, int Chead, int Ndst)
{
    extern __shared__ __align__(1024) char smem[];
    const uint32_t sb = smem_u32(smem);
    const int tid = threadIdx.x;
    const int lane = tid & 31, wid = tid >> 5;
    const int wm = wid & 3, wn = wid >> 2;
    const int bm = blockIdx.y * 128, bn = blockIdx.x * 128;

    int arow[2], asw[2];
#pragma unroll
    for (int mi = 0; mi < 2; mi++) {
        int r = wm * 32 + mi * 16 + (lane & 7) + ((lane >> 3) & 1) * 8;
        arow[mi] = r * 128;
        asw[mi] = (r & 7) << 4;
    }
    const uint32_t akadd = ((lane >> 4) & 1) * 16;
    int brow[4], bsw[4];
#pragma unroll
    for (int nb = 0; nb < 4; nb++) {
        int r = wn * 64 + nb * 16 + ((lane >> 4) & 1) * 8 + (lane & 7);
        brow[nb] = r * 128;
        bsw[nb] = (r & 7) << 4;
    }
    const uint32_t bkadd = ((lane >> 3) & 1) * 16;

    float acc[2][8][4];
#pragma unroll
    for (int mi = 0; mi < 2; mi++)
#pragma unroll
        for (int ni = 0; ni < 8; ni++)
#pragma unroll
            for (int q = 0; q < 4; q++) acc[mi][ni][q] = 0.f;

    const int nsc = Kst >> 7;    // superchunks = K/64

    gemm_load_super(A, B, M, Kst, bm, bn, 0, sb, tid); CP_COMMIT();
    if (nsc > 1) { gemm_load_super(A, B, M, Kst, bm, bn, 1, sb + TSTAGE, tid); CP_COMMIT(); }

    for (int sc = 0; sc < nsc; sc++) {
        if (sc + 1 < nsc) { CP_WAIT(1); } else { CP_WAIT(0); }
        __syncthreads();
        if (sc + 2 < nsc) {
            gemm_load_super(A, B, M, Kst, bm, bn, sc + 2, sb + ((sc + 2) % 3) * TSTAGE, tid);
            CP_COMMIT();
        }

        const uint32_t stage = sb + (sc % 3) * TSTAGE;
#pragma unroll
        for (int ks = 0; ks < 4; ks++) {
            const uint32_t k0b = ks * 32;
            uint32_t afh[2][4], afl[2][4];
#pragma unroll
            for (int mi = 0; mi < 2; mi++) {
                uint32_t off = arow[mi] + ((k0b + akadd) ^ (uint32_t)asw[mi]);
                LDMX4(afh[mi], stage + off);
                LDMX4(afl[mi], stage + 16384 + off);
            }
            uint32_t bfh[4][4], bfl[4][4];
#pragma unroll
            for (int nb = 0; nb < 4; nb++) {
                uint32_t off = brow[nb] + ((k0b + bkadd) ^ (uint32_t)bsw[nb]);
                LDMX4(bfh[nb], stage + 32768 + off);
                LDMX4(bfl[nb], stage + 49152 + off);
            }
            // term hh
#pragma unroll
            for (int mi = 0; mi < 2; mi++)
#pragma unroll
                for (int ni = 0; ni < 8; ni++) {
                    const int nb = ni >> 1, hf = ni & 1;
                    MMA16816(acc[mi][ni], afh[mi], bfh[nb][hf * 2], bfh[nb][hf * 2 + 1]);
                }
            // term lh
#pragma unroll
            for (int mi = 0; mi < 2; mi++)
#pragma unroll
                for (int ni = 0; ni < 8; ni++) {
                    const int nb = ni >> 1, hf = ni & 1;
                    MMA16816(acc[mi][ni], afl[mi], bfh[nb][hf * 2], bfh[nb][hf * 2 + 1]);
                }
            // term hl
#pragma unroll
            for (int mi = 0; mi < 2; mi++)
#pragma unroll
                for (int ni = 0; ni < 8; ni++) {
                    const int nb = ni >> 1, hf = ni & 1;
                    MMA16816(acc[mi][ni], afh[mi], bfl[nb][hf * 2], bfl[nb][hf * 2 + 1]);
                }
        }
    }
    __syncthreads();

    const int crow0 = bm + wm * 32 + (lane >> 2);
    const int ccol0 = bn + wn * 64 + (lane & 3) * 2;

    // ---- fused attention scores ----
    {
        const int head = (bn + wn * 64) / Chead;
        float psrc[2][2], pdst[2][2];
#pragma unroll
        for (int mi = 0; mi < 2; mi++)
#pragma unroll
            for (int hf = 0; hf < 2; hf++) { psrc[mi][hf] = 0.f; pdst[mi][hf] = 0.f; }
#pragma unroll
        for (int ni = 0; ni < 8; ni++) {
            int gc = ccol0 + ni * 8;
            float s0 = attS[gc], s1 = attS[gc + 1];
            float d0 = attD[gc], d1 = attD[gc + 1];
#pragma unroll
            for (int mi = 0; mi < 2; mi++)
#pragma unroll
                for (int hf = 0; hf < 2; hf++) {
                    psrc[mi][hf] = fmaf(acc[mi][ni][hf * 2], s0, fmaf(acc[mi][ni][hf * 2 + 1], s1, psrc[mi][hf]));
                    pdst[mi][hf] = fmaf(acc[mi][ni][hf * 2], d0, fmaf(acc[mi][ni][hf * 2 + 1], d1, pdst[mi][hf]));
                }
        }
#pragma unroll
        for (int mi = 0; mi < 2; mi++)
#pragma unroll
            for (int hf = 0; hf < 2; hf++) {
#pragma unroll
                for (int off = 1; off < 4; off <<= 1) {
                    psrc[mi][hf] += __shfl_xor_sync(0xffffffffu, psrc[mi][hf], off);
                    pdst[mi][hf] += __shfl_xor_sync(0xffffffffu, pdst[mi][hf], off);
                }
            }
        if ((lane & 3) == 0) {
#pragma unroll
            for (int mi = 0; mi < 2; mi++)
#pragma unroll
                for (int hf = 0; hf < 2; hf++) {
                    int row = crow0 + mi * 16 + hf * 8;
                    if (row < M) {
                        atomicAdd(&aS[(size_t)row * 8 + head], psrc[mi][hf]);
                        if (row < Ndst) atomicAdd(&aD[(size_t)row * 8 + head], pdst[mi][hf]);
                    }
                }
        }
    }

#pragma unroll
    for (int mi = 0; mi < 2; mi++)
#pragma unroll
        for (int hf = 0; hf < 2; hf++) {
            int row = crow0 + mi * 16 + hf * 8;
            if (row < M) {
                float* cp = C + (size_t)row * Nfull + ccol0;
#pragma unroll
                for (int ni = 0; ni < 8; ni++) {
                    float2 v = make_float2(acc[mi][ni][hf * 2], acc[mi][ni][hf * 2 + 1]);
                    *reinterpret_cast<float2*>(cp + ni * 8) = v;
                }
            }
        }
}

// ---------------- split-precision conversions ----------------
__global__ void conv_split_kernel(const float* __restrict__ X, __nv_bfloat16* __restrict__ Ap,
                                  int M, int K)
{
    size_t i = (size_t)blockIdx.x * blockDim.x + threadIdx.x;
    int kq = K >> 2;
    size_t total = (size_t)M * kq;
    if (i >= total) return;
    int m = (int)(i / kq);
    int k = (int)(i - (size_t)m * kq) << 2;
    float4 v = *reinterpret_cast<const float4*>(X + (size_t)m * K + k);
    float xs[4] = {v.x, v.y, v.z, v.w};
    __nv_bfloat16 hi[4], lo[4];
#pragma unroll
    for (int j = 0; j < 4; j++) {
        hi[j] = __float2bfloat16_rn(xs[j]);
        lo[j] = __float2bfloat16_rn(xs[j] - __bfloat162float(hi[j]));
    }
    __nv_bfloat162 h01, h23, l01, l23;
    h01.x = hi[0]; h01.y = hi[1]; h23.x = hi[2]; h23.y = hi[3];
    l01.x = lo[0]; l01.y = lo[1]; l23.x = lo[2]; l23.y = lo[3];
    __nv_bfloat16* b = Ap + (size_t)m * 2 * K;
    *reinterpret_cast<__nv_bfloat162*>(b + k) = h01;
    *reinterpret_cast<__nv_bfloat162*>(b + k + 2) = h23;
    *reinterpret_cast<__nv_bfloat162*>(b + K + k) = l01;
    *reinterpret_cast<__nv_bfloat162*>(b + K + k + 2) = l23;
}
// B' = [hi | lo]  (N x 2K) transposed from fp32 W (K x N)
__global__ void conv_wt_kernel(const float* __restrict__ W, __nv_bfloat16* __restrict__ Bp,
                               int K, int N)
{
    int idx = blockIdx.x * blockDim.x + threadIdx.x;
    if (idx >= K * N) return;
    int k = idx % K;
    int n = idx / K;
    float x = W[(size_t)k * N + n];
    __nv_bfloat16 hi = __float2bfloat16_rn(x);
    __nv_bfloat16 lo = __float2bfloat16_rn(x - __bfloat162float(hi));
    __nv_bfloat16* b = Bp + (size_t)n * 2 * K;
    b[k] = hi;
    b[K + k] = lo;
}

__global__ void zero2_kernel(float* p0, int n0, float* p1, int n1) {
    int i = blockIdx.x * blockDim.x + threadIdx.x;
    if (i < n0) p0[i] = 0.f;
    if (i < n1) p1[i] = 0.f;
}

// ---------------- CSR build (both layers fused) ----------------
__global__ void zero_deg_kernel(int* d1, int n1, int* d2, int n2) {
    int i = blockIdx.x * blockDim.x + threadIdx.x;
    if (i < n1) d1[i] = 0;
    if (i < n2) d2[i] = 0;
}
__global__ void hist2_kernel(const int* __restrict__ dstA, int EA, int* __restrict__ degA,
                             const int* __restrict__ dstB, int EB, int* __restrict__ degB)
{
    int i = blockIdx.x * blockDim.x + threadIdx.x;
    if (i < EA) atomicAdd(&degA[dstA[i]], 1);
    else {
        int j = i - EA;
        if (j < EB) atomicAdd(&degB[dstB[j]], 1);
    }
}
__global__ __launch_bounds__(1024) void scan2_kernel(
    const int* __restrict__ degA, int* __restrict__ rpA, int* __restrict__ curA, int nA,
    const int* __restrict__ degB, int* __restrict__ rpB, int* __restrict__ curB, int nB)
{
    const int* deg = blockIdx.x ? degB : degA;
    int* rowptr = blockIdx.x ? rpB : rpA;
    int* cursor = blockIdx.x ? curB : curA;
    int n = blockIdx.x ? nB : nA;
    __shared__ int sh[1024];
    int t = threadIdx.x;
    int per = (n + 1023) >> 10;
    int lo = t * per;
    int hi = min(lo + per, n);
    int s = 0;
    for (int i = lo; i < hi; i++) s += deg[i];
    sh[t] = s;
    __syncthreads();
    for (int off = 1; off < 1024; off <<= 1) {
        int v = (t >= off) ? sh[t - off] : 0;
        __syncthreads();
        sh[t] += v;
        __syncthreads();
    }
    int run = (t == 0) ? 0 : sh[t - 1];
    for (int i = lo; i < hi; i++) {
        rowptr[i] = run;
        cursor[i] = run;
        run += deg[i];
    }
    if (t == 0) rowptr[n] = sh[1023];
}
__global__ void scatter2_kernel(const int* __restrict__ srcA, const int* __restrict__ dstA, int EA,
                                int* __restrict__ curA, int* __restrict__ colA,
                                const int* __restrict__ srcB, const int* __restrict__ dstB, int EB,
                                int* __restrict__ curB, int* __restrict__ colB)
{
    int i = blockIdx.x * blockDim.x + threadIdx.x;
    if (i < EA) {
        int p = atomicAdd(&curA[dstA[i]], 1);
        colA[p] = srcA[i];
    } else {
        int j = i - EA;
        if (j < EB) {
            int p = atomicAdd(&curB[dstB[j]], 1);
            colB[p] = srcB[j];
        }
    }
}

// ---------------- layer 1 fused softmax + aggregate + bias + ELU -> bf16 split a2p ----------------
__global__ __launch_bounds__(128) void agg1_kernel(
    const float* __restrict__ h1, const float* __restrict__ asrc,
    const float* __restrict__ adst, const int* __restrict__ rowptr,
    const int* __restrict__ col, const float* __restrict__ bias,
    __nv_bfloat16* __restrict__ a2p)
{
    const int n = blockIdx.x;
    const int t = threadIdx.x;
    const int warp = t >> 5, lane = t & 31;
    __shared__ float sadst[8], sm[8], ss[8];
    __shared__ float red[4][8];
    __shared__ float salpha[16 * 8];
    __shared__ int scol[16];

    const int start = rowptr[n], end = rowptr[n + 1];
    if (t < 8) sadst[t] = adst[n * 8 + t];
    __syncthreads();

    float lm[8];
#pragma unroll
    for (int h = 0; h < 8; h++) lm[h] = -1e30f;
    for (int j = start + t; j < end; j += 128) {
        const float* ap = asrc + (size_t)col[j] * 8;
#pragma unroll
        for (int h = 0; h < 8; h++) {
            float e = ap[h] + sadst[h];
            e = e > 0.f ? e : NEG_SLOPE * e;
            lm[h] = fmaxf(lm[h], e);
        }
    }
#pragma unroll
    for (int h = 0; h < 8; h++)
#pragma unroll
        for (int off = 16; off > 0; off >>= 1)
            lm[h] = fmaxf(lm[h], __shfl_xor_sync(0xffffffffu, lm[h], off));
    if (lane == 0)
#pragma unroll
        for (int h = 0; h < 8; h++) red[warp][h] = lm[h];
    __syncthreads();
    if (t < 8) sm[t] = fmaxf(fmaxf(red[0][t], red[1][t]), fmaxf(red[2][t], red[3][t]));
    __syncthreads();

    float lsum[8];
#pragma unroll
    for (int h = 0; h < 8; h++) lsum[h] = 0.f;
    for (int j = start + t; j < end; j += 128) {
        const float* ap = asrc + (size_t)col[j] * 8;
#pragma unroll
        for (int h = 0; h < 8; h++) {
            float e = ap[h] + sadst[h];
            e = e > 0.f ? e : NEG_SLOPE * e;
            lsum[h] += expf(e - sm[h]);
        }
    }
#pragma unroll
    for (int h = 0; h < 8; h++)
#pragma unroll
        for (int off = 16; off > 0; off >>= 1)
            lsum[h] += __shfl_xor_sync(0xffffffffu, lsum[h], off);
    if (lane == 0)
#pragma unroll
        for (int h = 0; h < 8; h++) red[warp][h] = lsum[h];
    __syncthreads();
    if (t < 8) ss[t] = red[0][t] + red[1][t] + red[2][t] + red[3][t];
    __syncthreads();

    float acc0 = 0.f, acc1 = 0.f, acc2 = 0.f, acc3 = 0.f;
    const int head = t >> 4;
    const int c4 = t << 2;
    for (int base = start; base < end; base += 16) {
        int cnt = min(16, end - base);
        if (t < cnt) scol[t] = col[base + t];
        if (t < cnt * 8) {
            int j = base + (t >> 3);
            int h = t & 7;
            float e = asrc[(size_t)col[j] * 8 + h] + sadst[h];
            e = e > 0.f ? e : NEG_SLOPE * e;
            salpha[t] = expf(e - sm[h]) / ss[h];
        }
        __syncthreads();
        for (int q = 0; q < cnt; q++) {
            int s = scol[q];
            float a = salpha[q * 8 + head];
            float4 v = *reinterpret_cast<const float4*>(h1 + (size_t)s * HC1 + c4);
            acc0 = fmaf(a, v.x, acc0);
            acc1 = fmaf(a, v.y, acc1);
            acc2 = fmaf(a, v.z, acc2);
            acc3 = fmaf(a, v.w, acc3);
        }
        __syncthreads();
    }
    // bias + ELU + bf16 split store to a2p [hi 512 | lo 512]
    float o[4] = {acc0, acc1, acc2, acc3};
    __nv_bfloat16 hi[4], lo[4];
#pragma unroll
    for (int i = 0; i < 4; i++) {
        float v = o[i] + bias[c4 + i];
        v = v > 0.f ? v : expm1f(v);
        hi[i] = __float2bfloat16_rn(v);
        lo[i] = __float2bfloat16_rn(v - __bfloat162float(hi[i]));
    }
    __nv_bfloat162 h01, h23, l01, l23;
    h01.x = hi[0]; h01.y = hi[1]; h23.x = hi[2]; h23.y = hi[3];
    l01.x = lo[0]; l01.y = lo[1]; l23.x = lo[2]; l23.y = lo[3];
    __nv_bfloat16* b = a2p + (size_t)n * KS2;
    *reinterpret_cast<__nv_bfloat162*>(b + c4) = h01;
    *reinterpret_cast<__nv_bfloat162*>(b + c4 + 2) = h23;
    *reinterpret_cast<__nv_bfloat162*>(b + HC1 + c4) = l01;
    *reinterpret_cast<__nv_bfloat162*>(b + HC1 + c4 + 2) = l23;
}

// ---------------- layer 2 fused softmax + aggregate + head-mean + bias ----------------
__global__ __launch_bounds__(256) void agg2_kernel(
    const float* __restrict__ h2, const float* __restrict__ asrc,
    const float* __restrict__ adst, const int* __restrict__ rowptr,
    const int* __restrict__ col, const float* __restrict__ bias,
    float* __restrict__ out)
{
    const int n = blockIdx.x;
    const int t = threadIdx.x;
    const int warp = t >> 5, lane = t & 31;
    __shared__ float sadst[8], sm[8], ss[8];
    __shared__ float red[8][8];
    __shared__ float salpha[32 * 8];
    __shared__ int scol[32];

    const int start = rowptr[n], end = rowptr[n + 1];
    if (t < 8) sadst[t] = adst[n * 8 + t];
    __syncthreads();

    float lm[8];
#pragma unroll
    for (int h = 0; h < 8; h++) lm[h] = -1e30f;
    for (int j = start + t; j < end; j += 256) {
        const float* ap = asrc + (size_t)col[j] * 8;
#pragma unroll
        for (int h = 0; h < 8; h++) {
            float e = ap[h] + sadst[h];
            e = e > 0.f ? e : NEG_SLOPE * e;
            lm[h] = fmaxf(lm[h], e);
        }
    }
#pragma unroll
    for (int h = 0; h < 8; h++)
#pragma unroll
        for (int off = 16; off > 0; off >>= 1)
            lm[h] = fmaxf(lm[h], __shfl_xor_sync(0xffffffffu, lm[h], off));
    if (lane == 0)
#pragma unroll
        for (int h = 0; h < 8; h++) red[warp][h] = lm[h];
    __syncthreads();
    if (t < 8) {
        float m = red[0][t];
#pragma unroll
        for (int w = 1; w < 8; w++) m = fmaxf(m, red[w][t]);
        sm[t] = m;
    }
    __syncthreads();

    float lsum[8];
#pragma unroll
    for (int h = 0; h < 8; h++) lsum[h] = 0.f;
    for (int j = start + t; j < end; j += 256) {
        const float* ap = asrc + (size_t)col[j] * 8;
#pragma unroll
        for (int h = 0; h < 8; h++) {
            float e = ap[h] + sadst[h];
            e = e > 0.f ? e : NEG_SLOPE * e;
            lsum[h] += expf(e - sm[h]);
        }
    }
#pragma unroll
    for (int h = 0; h < 8; h++)
#pragma unroll
        for (int off = 16; off > 0; off >>= 1)
            lsum[h] += __shfl_xor_sync(0xffffffffu, lsum[h], off);
    if (lane == 0)
#pragma unroll
        for (int h = 0; h < 8; h++) red[warp][h] = lsum[h];
    __syncthreads();
    if (t < 8) {
        float s = 0.f;
#pragma unroll
        for (int w = 0; w < 8; w++) s += red[w][t];
        ss[t] = s;
    }
    __syncthreads();

    float acc[8];
#pragma unroll
    for (int h = 0; h < 8; h++) acc[h] = 0.f;
    for (int base = start; base < end; base += 32) {
        int cnt = min(32, end - base);
        if (t < cnt) scol[t] = col[base + t];
        if (t < cnt * 8) {
            int j = base + (t >> 3);
            int h = t & 7;
            float e = asrc[(size_t)col[j] * 8 + h] + sadst[h];
            e = e > 0.f ? e : NEG_SLOPE * e;
            salpha[t] = expf(e - sm[h]) / ss[h];
        }
        __syncthreads();
        for (int q = 0; q < cnt; q++) {
            const float* hp = h2 + (size_t)scol[q] * HC2 + t;
#pragma unroll
            for (int h = 0; h < 8; h++)
                acc[h] = fmaf(salpha[q * 8 + h], hp[h * C2], acc[h]);
        }
        __syncthreads();
    }
    float s = 0.f;
#pragma unroll
    for (int h = 0; h < 8; h++) s += acc[h];
    out[(size_t)n * C2 + t] = 0.125f * s + bias[t];
}

// ---------------- host ----------------
extern "C" void kernel_launch(void* const* d_in, const int* in_sizes, int n_in,
                              void* d_out, int out_size)
{
    const float* x        = (const float*)d_in[0];
    const int*   src1     = (const int*)d_in[1];
    const int*   dst1     = (const int*)d_in[2];
    const int*   src2     = (const int*)d_in[3];
    const int*   dst2     = (const int*)d_in[4];
    const float* W1       = (const float*)d_in[5];
    const float* att_src1 = (const float*)d_in[6];
    const float* att_dst1 = (const float*)d_in[7];
    const float* b1       = (const float*)d_in[8];
    const float* W2       = (const float*)d_in[9];
    const float* att_src2 = (const float*)d_in[10];
    const float* att_dst2 = (const float*)d_in[11];
    const float* b2       = (const float*)d_in[12];
    float* out = (float*)d_out;

    const int E1 = in_sizes[1];
    const int E2 = in_sizes[3];

    float *h1, *h2, *as1, *ad1, *as2, *ad2;
    int *deg1, *rp1, *cur1, *col1, *deg2, *rp2, *cur2, *col2;
    __nv_bfloat16 *a1p, *b1p, *a2p, *b2p;
    cudaGetSymbolAddress((void**)&h1, g_h1);
    cudaGetSymbolAddress((void**)&h2, g_h2);
    cudaGetSymbolAddress((void**)&as1, g_as1);
    cudaGetSymbolAddress((void**)&ad1, g_ad1);
    cudaGetSymbolAddress((void**)&as2, g_as2);
    cudaGetSymbolAddress((void**)&ad2, g_ad2);
    cudaGetSymbolAddress((void**)&deg1, g_deg1);
    cudaGetSymbolAddress((void**)&rp1, g_rp1);
    cudaGetSymbolAddress((void**)&cur1, g_cur1);
    cudaGetSymbolAddress((void**)&col1, g_col1);
    cudaGetSymbolAddress((void**)&deg2, g_deg2);
    cudaGetSymbolAddress((void**)&rp2, g_rp2);
    cudaGetSymbolAddress((void**)&cur2, g_cur2);
    cudaGetSymbolAddress((void**)&col2, g_col2);
    cudaGetSymbolAddress((void**)&a1p, g_a1p);
    cudaGetSymbolAddress((void**)&b1p, g_b1p);
    cudaGetSymbolAddress((void**)&a2p, g_a2p);
    cudaGetSymbolAddress((void**)&b2p, g_b2p);

    cudaFuncSetAttribute(gemm_mma, cudaFuncAttributeMaxDynamicSharedMemorySize, SMEM_GEMM);

    // ---- layer 1 ----  (GEMM1 stays launch #4 for ncu capture)
    {
        size_t tot = (size_t)N0 * (D / 4);
        conv_split_kernel<<<(unsigned)((tot + 255) / 256), 256>>>(x, a1p, N0, D);       // 1
    }
    conv_wt_kernel<<<(D * HC1 + 255) / 256, 256>>>(W1, b1p, D, HC1);                     // 2
    zero2_kernel<<<(N0 * H1 + 255) / 256, 256>>>(as1, N0 * H1, ad1, N1 * H1);            // 3
    {
        dim3 grid(HC1 / 128, (N0 + 127) / 128);
        gemm_mma<<<grid, 256, SMEM_GEMM>>>(a1p, b1p, h1, N0, HC1, KS1,                   // 4 (profiled)
                                           att_src1, att_dst1, as1, ad1, C1, N1);
    }

    // ---- fused CSR build (both layers) ----
    zero_deg_kernel<<<(N1 + 255) / 256, 256>>>(deg1, N1, deg2, N2);
    hist2_kernel<<<(E1 + E2 + 255) / 256, 256>>>(dst1, E1, deg1, dst2, E2, deg2);
    scan2_kernel<<<2, 1024>>>(deg1, rp1, cur1, N1, deg2, rp2, cur2, N2);
    scatter2_kernel<<<(E1 + E2 + 255) / 256, 256>>>(src1, dst1, E1, cur1, col1,
                                                    src2, dst2, E2, cur2, col2);

    agg1_kernel<<<N1, 128>>>(h1, as1, ad1, rp1, col1, b1, a2p);

    // ---- layer 2 ----
    conv_wt_kernel<<<(HC1 * HC2 + 255) / 256, 256>>>(W2, b2p, HC1, HC2);
    zero2_kernel<<<(N1 * H2 + 255) / 256, 256>>>(as2, N1 * H2, ad2, N2 * H2);
    {
        dim3 grid(HC2 / 128, (N1 + 127) / 128);
        gemm_mma<<<grid, 256, SMEM_GEMM>>>(a2p, b2p, h2, N1, HC2, KS2,
                                           att_src2, att_dst2, as2, ad2, C2, N2);
    }

    agg2_kernel<<<N2, 256>>>(h2, as2, ad2, rp2, col2, b2, out);

    (void)n_in; (void)out_size;
}

// round 10
// speedup vs baseline: 1.0196x; 1.0196x over previous
#include <cuda_runtime.h>
#include <cuda_bf16.h>
#include <cstdint>
#include <math.h>

// ---------------- problem constants ----------------
#define N0 120000
#define N1 24000
#define N2 6000
#define D  256
#define H1 8
#define C1 64
#define HC1 (H1*C1)     // 512
#define H2 8
#define C2 256
#define HC2 (H2*C2)     // 2048
#define E1MAX 384000
#define E2MAX 96000
#define NEG_SLOPE 0.2f

#define KS1 (2*D)       // 512  layer1 A/B storage K (hi|lo)
#define KS2 (2*HC1)     // 1024 layer2

// ---------------- scratch (static device globals; no allocation) ----------------
__device__ float g_h1[(size_t)N0 * HC1];     // 245.8 MB
__device__ float g_h2[(size_t)N1 * HC2];     // 196.6 MB
__device__ float g_as1[(size_t)N0 * H1];
__device__ float g_ad1[(size_t)N1 * H1];
__device__ float g_as2[(size_t)N1 * H2];
__device__ float g_ad2[(size_t)N2 * H2];
__device__ int g_deg1[N1];
__device__ int g_rp1[N1 + 1];
__device__ int g_cur1[N1];
__device__ int g_col1[E1MAX];
__device__ int g_deg2[N2];
__device__ int g_rp2[N2 + 1];
__device__ int g_cur2[N2];
__device__ int g_col2[E2MAX];
// split-precision bf16 operands [hi|lo]
__device__ __nv_bfloat16 g_a1p[(size_t)N0 * KS1];   // 122.9 MB
__device__ __nv_bfloat16 g_b1p[(size_t)HC1 * KS1];  //  0.5 MB
__device__ __nv_bfloat16 g_a2p[(size_t)N1 * KS2];   //  49.2 MB
__device__ __nv_bfloat16 g_b2p[(size_t)HC2 * KS2];  //  4.2 MB

// ================= PTX helpers =================
__device__ __forceinline__ uint32_t smem_u32(const void* p) {
    uint32_t a;
    asm("{ .reg .u64 t; cvta.to.shared.u64 t, %1; cvt.u32.u64 %0, t; }" : "=r"(a) : "l"(p));
    return a;
}
#define CP_ASYNC16(sp, gp) \
    asm volatile("cp.async.cg.shared.global [%0], [%1], 16;" :: "r"(sp), "l"(gp) : "memory")
#define CP_COMMIT() asm volatile("cp.async.commit_group;" ::: "memory")
#define CP_WAIT(n)  asm volatile("cp.async.wait_group %0;" :: "n"(n) : "memory")
#define LDMX4(r, addr) \
    asm volatile("ldmatrix.sync.aligned.m8n8.x4.shared.b16 {%0,%1,%2,%3}, [%4];" \
        : "=r"((r)[0]), "=r"((r)[1]), "=r"((r)[2]), "=r"((r)[3]) : "r"(addr))
#define MMA16816(d, a, b0v, b1v) \
    asm volatile("mma.sync.aligned.m16n8k16.row.col.f32.bf16.bf16.f32 " \
        "{%0,%1,%2,%3}, {%4,%5,%6,%7}, {%8,%9}, {%0,%1,%2,%3};" \
        : "+f"((d)[0]), "+f"((d)[1]), "+f"((d)[2]), "+f"((d)[3]) \
        : "r"((a)[0]), "r"((a)[1]), "r"((a)[2]), "r"((a)[3]), "r"(b0v), "r"(b1v))

// ================= bf16 mma.sync GEMM, K32-interleaved 3-term split, fused scores ====
// A stored [M, 2K] = [hi|lo], B stored [Nfull, 2K] = [hi|lo].
// Superchunk sc = one 32-wide K column. SMEM row (128B) = [hi 64B | lo 64B] for
// the same logical row -> all four tiles {A_hi,A_lo,B_hi,B_lo} resident in a
// 32KB stage. All 3 split terms (hh, lh, hl) computed per residency
// (-33% smem traffic/MAC vs R8) while keeping 3x32KB stages -> 2 CTAs/SM.
#define TSTAGE 32768
#define SMEM_GEMM (3 * TSTAGE)

__device__ __forceinline__ void gemm_load_super(
    const __nv_bfloat16* __restrict__ A, const __nv_bfloat16* __restrict__ B,
    int M, int Kst, int bm, int bn, int sc, uint32_t stbase, int tid)
{
    const int K = Kst >> 1;
    const int coff = sc << 5;       // 32 elements per chunk
    const int r0 = tid >> 3;
    const int kseg = tid & 7;       // 0-3: hi half, 4-7: lo half
    const int goff = (kseg < 4) ? (coff + kseg * 8) : (K + coff + (kseg - 4) * 8);
    const uint32_t kb = (uint32_t)(kseg * 16);
#pragma unroll
    for (int i = 0; i < 4; i++) {
        int row = r0 + i * 32;
        int grow = bm + row; if (grow >= M) grow = M - 1;
        const void* gp = (const void*)(A + (size_t)grow * Kst + goff);
        uint32_t sp = stbase + (uint32_t)(row * 128) + (kb ^ (uint32_t)((row & 7) << 4));
        CP_ASYNC16(sp, gp);
    }
#pragma unroll
    for (int i = 0; i < 4; i++) {
        int row = r0 + i * 32;
        const void* gp = (const void*)(B + (size_t)(bn + row) * Kst + goff);
        uint32_t sp = stbase + 16384 + (uint32_t)(row * 128) + (kb ^ (uint32_t)((row & 7) << 4));
        CP_ASYNC16(sp, gp);
    }
}

__global__ __launch_bounds__(256, 2) void gemm_mma(
    const __nv_bfloat16* __restrict__ A, const __nv_bfloat16* __restrict__ B,
    float* __restrict__ C, int M, int Nfull, int Kst,
    const float* __restrict__ attS, const float* __restrict__ attD,
    float* __restrict__ aS, float* __restrict__ aD, int Chead, int Ndst)
{
    extern __shared__ __align__(1024) char smem[];
    const uint32_t sb = smem_u32(smem);
    const int tid = threadIdx.x;
    const int lane = tid & 31, wid = tid >> 5;
    const int wm = wid & 3, wn = wid >> 2;
    const int bm = blockIdx.y * 128, bn = blockIdx.x * 128;

    int arow[2], asw[2];
#pragma unroll
    for (int mi = 0; mi < 2; mi++) {
        int r = wm * 32 + mi * 16 + (lane & 7) + ((lane >> 3) & 1) * 8;
        arow[mi] = r * 128;
        asw[mi] = (r & 7) << 4;
    }
    const uint32_t akadd = ((lane >> 4) & 1) * 16;
    int brow[4], bsw[4];
#pragma unroll
    for (int nb = 0; nb < 4; nb++) {
        int r = wn * 64 + nb * 16 + ((lane >> 4) & 1) * 8 + (lane & 7);
        brow[nb] = r * 128;
        bsw[nb] = (r & 7) << 4;
    }
    const uint32_t bkadd = ((lane >> 3) & 1) * 16;

    float acc[2][8][4];
#pragma unroll
    for (int mi = 0; mi < 2; mi++)
#pragma unroll
        for (int ni = 0; ni < 8; ni++)
#pragma unroll
            for (int q = 0; q < 4; q++) acc[mi][ni][q] = 0.f;

    const int nsc = Kst >> 6;    // superchunks = K/32

    gemm_load_super(A, B, M, Kst, bm, bn, 0, sb, tid); CP_COMMIT();
    gemm_load_super(A, B, M, Kst, bm, bn, 1, sb + TSTAGE, tid); CP_COMMIT();

    for (int sc = 0; sc < nsc; sc++) {
        if (sc + 1 < nsc) { CP_WAIT(1); } else { CP_WAIT(0); }
        __syncthreads();
        if (sc + 2 < nsc) {
            gemm_load_super(A, B, M, Kst, bm, bn, sc + 2, sb + ((sc + 2) % 3) * TSTAGE, tid);
            CP_COMMIT();
        }

        const uint32_t stage = sb + (sc % 3) * TSTAGE;
#pragma unroll
        for (int ks = 0; ks < 2; ks++) {
            const uint32_t k0b = ks * 32;        // hi bytes [0,64); lo = +64
            uint32_t afh[2][4], afl[2][4];
#pragma unroll
            for (int mi = 0; mi < 2; mi++) {
                uint32_t ah = (k0b + akadd) ^ (uint32_t)asw[mi];
                uint32_t al = (64 + k0b + akadd) ^ (uint32_t)asw[mi];
                LDMX4(afh[mi], stage + arow[mi] + ah);
                LDMX4(afl[mi], stage + arow[mi] + al);
            }
            uint32_t bf[4][4];
            // B_hi frags
#pragma unroll
            for (int nb = 0; nb < 4; nb++) {
                uint32_t bh = (k0b + bkadd) ^ (uint32_t)bsw[nb];
                LDMX4(bf[nb], stage + 16384 + brow[nb] + bh);
            }
            // terms hh + lh against B_hi
#pragma unroll
            for (int mi = 0; mi < 2; mi++)
#pragma unroll
                for (int ni = 0; ni < 8; ni++) {
                    const int nb = ni >> 1, hf = ni & 1;
                    MMA16816(acc[mi][ni], afh[mi], bf[nb][hf * 2], bf[nb][hf * 2 + 1]);
                }
#pragma unroll
            for (int mi = 0; mi < 2; mi++)
#pragma unroll
                for (int ni = 0; ni < 8; ni++) {
                    const int nb = ni >> 1, hf = ni & 1;
                    MMA16816(acc[mi][ni], afl[mi], bf[nb][hf * 2], bf[nb][hf * 2 + 1]);
                }
            // B_lo frags (overwrite bf), term hl
#pragma unroll
            for (int nb = 0; nb < 4; nb++) {
                uint32_t bl = (64 + k0b + bkadd) ^ (uint32_t)bsw[nb];
                LDMX4(bf[nb], stage + 16384 + brow[nb] + bl);
            }
#pragma unroll
            for (int mi = 0; mi < 2; mi++)
#pragma unroll
                for (int ni = 0; ni < 8; ni++) {
                    const int nb = ni >> 1, hf = ni & 1;
                    MMA16816(acc[mi][ni], afh[mi], bf[nb][hf * 2], bf[nb][hf * 2 + 1]);
                }
        }
    }
    __syncthreads();

    const int crow0 = bm + wm * 32 + (lane >> 2);
    const int ccol0 = bn + wn * 64 + (lane & 3) * 2;

    // ---- fused attention scores ----
    {
        const int head = (bn + wn * 64) / Chead;
        float psrc[2][2], pdst[2][2];
#pragma unroll
        for (int mi = 0; mi < 2; mi++)
#pragma unroll
            for (int hf = 0; hf < 2; hf++) { psrc[mi][hf] = 0.f; pdst[mi][hf] = 0.f; }
#pragma unroll
        for (int ni = 0; ni < 8; ni++) {
            int gc = ccol0 + ni * 8;
            float s0 = attS[gc], s1 = attS[gc + 1];
            float d0 = attD[gc], d1 = attD[gc + 1];
#pragma unroll
            for (int mi = 0; mi < 2; mi++)
#pragma unroll
                for (int hf = 0; hf < 2; hf++) {
                    psrc[mi][hf] = fmaf(acc[mi][ni][hf * 2], s0, fmaf(acc[mi][ni][hf * 2 + 1], s1, psrc[mi][hf]));
                    pdst[mi][hf] = fmaf(acc[mi][ni][hf * 2], d0, fmaf(acc[mi][ni][hf * 2 + 1], d1, pdst[mi][hf]));
                }
        }
#pragma unroll
        for (int mi = 0; mi < 2; mi++)
#pragma unroll
            for (int hf = 0; hf < 2; hf++) {
#pragma unroll
                for (int off = 1; off < 4; off <<= 1) {
                    psrc[mi][hf] += __shfl_xor_sync(0xffffffffu, psrc[mi][hf], off);
                    pdst[mi][hf] += __shfl_xor_sync(0xffffffffu, pdst[mi][hf], off);
                }
            }
        if ((lane & 3) == 0) {
#pragma unroll
            for (int mi = 0; mi < 2; mi++)
#pragma unroll
                for (int hf = 0; hf < 2; hf++) {
                    int row = crow0 + mi * 16 + hf * 8;
                    if (row < M) {
                        atomicAdd(&aS[(size_t)row * 8 + head], psrc[mi][hf]);
                        if (row < Ndst) atomicAdd(&aD[(size_t)row * 8 + head], pdst[mi][hf]);
                    }
                }
        }
    }

#pragma unroll
    for (int mi = 0; mi < 2; mi++)
#pragma unroll
        for (int hf = 0; hf < 2; hf++) {
            int row = crow0 + mi * 16 + hf * 8;
            if (row < M) {
                float* cp = C + (size_t)row * Nfull + ccol0;
#pragma unroll
                for (int ni = 0; ni < 8; ni++) {
                    float2 v = make_float2(acc[mi][ni][hf * 2], acc[mi][ni][hf * 2 + 1]);
                    *reinterpret_cast<float2*>(cp + ni * 8) = v;
                }
            }
        }
}

// ---------------- split-precision conversions ----------------
__global__ void conv_split_kernel(const float* __restrict__ X, __nv_bfloat16* __restrict__ Ap,
                                  int M, int K)
{
    size_t i = (size_t)blockIdx.x * blockDim.x + threadIdx.x;
    int kq = K >> 2;
    size_t total = (size_t)M * kq;
    if (i >= total) return;
    int m = (int)(i / kq);
    int k = (int)(i - (size_t)m * kq) << 2;
    float4 v = *reinterpret_cast<const float4*>(X + (size_t)m * K + k);
    float xs[4] = {v.x, v.y, v.z, v.w};
    __nv_bfloat16 hi[4], lo[4];
#pragma unroll
    for (int j = 0; j < 4; j++) {
        hi[j] = __float2bfloat16_rn(xs[j]);
        lo[j] = __float2bfloat16_rn(xs[j] - __bfloat162float(hi[j]));
    }
    __nv_bfloat162 h01, h23, l01, l23;
    h01.x = hi[0]; h01.y = hi[1]; h23.x = hi[2]; h23.y = hi[3];
    l01.x = lo[0]; l01.y = lo[1]; l23.x = lo[2]; l23.y = lo[3];
    __nv_bfloat16* b = Ap + (size_t)m * 2 * K;
    *reinterpret_cast<__nv_bfloat162*>(b + k) = h01;
    *reinterpret_cast<__nv_bfloat162*>(b + k + 2) = h23;
    *reinterpret_cast<__nv_bfloat162*>(b + K + k) = l01;
    *reinterpret_cast<__nv_bfloat162*>(b + K + k + 2) = l23;
}
// B' = [hi | lo]  (N x 2K) transposed from fp32 W (K x N)
__global__ void conv_wt_kernel(const float* __restrict__ W, __nv_bfloat16* __restrict__ Bp,
                               int K, int N)
{
    int idx = blockIdx.x * blockDim.x + threadIdx.x;
    if (idx >= K * N) return;
    int k = idx % K;
    int n = idx / K;
    float x = W[(size_t)k * N + n];
    __nv_bfloat16 hi = __float2bfloat16_rn(x);
    __nv_bfloat16 lo = __float2bfloat16_rn(x - __bfloat162float(hi));
    __nv_bfloat16* b = Bp + (size_t)n * 2 * K;
    b[k] = hi;
    b[K + k] = lo;
}

__global__ void zero2_kernel(float* p0, int n0, float* p1, int n1) {
    int i = blockIdx.x * blockDim.x + threadIdx.x;
    if (i < n0) p0[i] = 0.f;
    if (i < n1) p1[i] = 0.f;
}

// ---------------- CSR build (both layers fused) ----------------
__global__ void zero_deg_kernel(int* d1, int n1, int* d2, int n2) {
    int i = blockIdx.x * blockDim.x + threadIdx.x;
    if (i < n1) d1[i] = 0;
    if (i < n2) d2[i] = 0;
}
__global__ void hist2_kernel(const int* __restrict__ dstA, int EA, int* __restrict__ degA,
                             const int* __restrict__ dstB, int EB, int* __restrict__ degB)
{
    int i = blockIdx.x * blockDim.x + threadIdx.x;
    if (i < EA) atomicAdd(&degA[dstA[i]], 1);
    else {
        int j = i - EA;
        if (j < EB) atomicAdd(&degB[dstB[j]], 1);
    }
}
__global__ __launch_bounds__(1024) void scan2_kernel(
    const int* __restrict__ degA, int* __restrict__ rpA, int* __restrict__ curA, int nA,
    const int* __restrict__ degB, int* __restrict__ rpB, int* __restrict__ curB, int nB)
{
    const int* deg = blockIdx.x ? degB : degA;
    int* rowptr = blockIdx.x ? rpB : rpA;
    int* cursor = blockIdx.x ? curB : curA;
    int n = blockIdx.x ? nB : nA;
    __shared__ int sh[1024];
    int t = threadIdx.x;
    int per = (n + 1023) >> 10;
    int lo = t * per;
    int hi = min(lo + per, n);
    int s = 0;
    for (int i = lo; i < hi; i++) s += deg[i];
    sh[t] = s;
    __syncthreads();
    for (int off = 1; off < 1024; off <<= 1) {
        int v = (t >= off) ? sh[t - off] : 0;
        __syncthreads();
        sh[t] += v;
        __syncthreads();
    }
    int run = (t == 0) ? 0 : sh[t - 1];
    for (int i = lo; i < hi; i++) {
        rowptr[i] = run;
        cursor[i] = run;
        run += deg[i];
    }
    if (t == 0) rowptr[n] = sh[1023];
}
__global__ void scatter2_kernel(const int* __restrict__ srcA, const int* __restrict__ dstA, int EA,
                                int* __restrict__ curA, int* __restrict__ colA,
                                const int* __restrict__ srcB, const int* __restrict__ dstB, int EB,
                                int* __restrict__ curB, int* __restrict__ colB)
{
    int i = blockIdx.x * blockDim.x + threadIdx.x;
    if (i < EA) {
        int p = atomicAdd(&curA[dstA[i]], 1);
        colA[p] = srcA[i];
    } else {
        int j = i - EA;
        if (j < EB) {
            int p = atomicAdd(&curB[dstB[j]], 1);
            colB[p] = srcB[j];
        }
    }
}

// ---------------- layer 1 fused softmax + aggregate + bias + ELU -> bf16 split a2p ----------------
__global__ __launch_bounds__(128) void agg1_kernel(
    const float* __restrict__ h1, const float* __restrict__ asrc,
    const float* __restrict__ adst, const int* __restrict__ rowptr,
    const int* __restrict__ col, const float* __restrict__ bias,
    __nv_bfloat16* __restrict__ a2p)
{
    const int n = blockIdx.x;
    const int t = threadIdx.x;
    const int warp = t >> 5, lane = t & 31;
    __shared__ float sadst[8], sm[8], ss[8];
    __shared__ float red[4][8];
    __shared__ float salpha[16 * 8];
    __shared__ int scol[16];

    const int start = rowptr[n], end = rowptr[n + 1];
    if (t < 8) sadst[t] = adst[n * 8 + t];
    __syncthreads();

    float lm[8];
#pragma unroll
    for (int h = 0; h < 8; h++) lm[h] = -1e30f;
    for (int j = start + t; j < end; j += 128) {
        const float* ap = asrc + (size_t)col[j] * 8;
#pragma unroll
        for (int h = 0; h < 8; h++) {
            float e = ap[h] + sadst[h];
            e = e > 0.f ? e : NEG_SLOPE * e;
            lm[h] = fmaxf(lm[h], e);
        }
    }
#pragma unroll
    for (int h = 0; h < 8; h++)
#pragma unroll
        for (int off = 16; off > 0; off >>= 1)
            lm[h] = fmaxf(lm[h], __shfl_xor_sync(0xffffffffu, lm[h], off));
    if (lane == 0)
#pragma unroll
        for (int h = 0; h < 8; h++) red[warp][h] = lm[h];
    __syncthreads();
    if (t < 8) sm[t] = fmaxf(fmaxf(red[0][t], red[1][t]), fmaxf(red[2][t], red[3][t]));
    __syncthreads();

    float lsum[8];
#pragma unroll
    for (int h = 0; h < 8; h++) lsum[h] = 0.f;
    for (int j = start + t; j < end; j += 128) {
        const float* ap = asrc + (size_t)col[j] * 8;
#pragma unroll
        for (int h = 0; h < 8; h++) {
            float e = ap[h] + sadst[h];
            e = e > 0.f ? e : NEG_SLOPE * e;
            lsum[h] += expf(e - sm[h]);
        }
    }
#pragma unroll
    for (int h = 0; h < 8; h++)
#pragma unroll
        for (int off = 16; off > 0; off >>= 1)
            lsum[h] += __shfl_xor_sync(0xffffffffu, lsum[h], off);
    if (lane == 0)
#pragma unroll
        for (int h = 0; h < 8; h++) red[warp][h] = lsum[h];
    __syncthreads();
    if (t < 8) ss[t] = red[0][t] + red[1][t] + red[2][t] + red[3][t];
    __syncthreads();

    float acc0 = 0.f, acc1 = 0.f, acc2 = 0.f, acc3 = 0.f;
    const int head = t >> 4;
    const int c4 = t << 2;
    for (int base = start; base < end; base += 16) {
        int cnt = min(16, end - base);
        if (t < cnt) scol[t] = col[base + t];
        if (t < cnt * 8) {
            int j = base + (t >> 3);
            int h = t & 7;
            float e = asrc[(size_t)col[j] * 8 + h] + sadst[h];
            e = e > 0.f ? e : NEG_SLOPE * e;
            salpha[t] = expf(e - sm[h]) / ss[h];
        }
        __syncthreads();
        for (int q = 0; q < cnt; q++) {
            int s = scol[q];
            float a = salpha[q * 8 + head];
            float4 v = *reinterpret_cast<const float4*>(h1 + (size_t)s * HC1 + c4);
            acc0 = fmaf(a, v.x, acc0);
            acc1 = fmaf(a, v.y, acc1);
            acc2 = fmaf(a, v.z, acc2);
            acc3 = fmaf(a, v.w, acc3);
        }
        __syncthreads();
    }
    // bias + ELU + bf16 split store to a2p [hi 512 | lo 512]
    float o[4] = {acc0, acc1, acc2, acc3};
    __nv_bfloat16 hi[4], lo[4];
#pragma unroll
    for (int i = 0; i < 4; i++) {
        float v = o[i] + bias[c4 + i];
        v = v > 0.f ? v : expm1f(v);
        hi[i] = __float2bfloat16_rn(v);
        lo[i] = __float2bfloat16_rn(v - __bfloat162float(hi[i]));
    }
    __nv_bfloat162 h01, h23, l01, l23;
    h01.x = hi[0]; h01.y = hi[1]; h23.x = hi[2]; h23.y = hi[3];
    l01.x = lo[0]; l01.y = lo[1]; l23.x = lo[2]; l23.y = lo[3];
    __nv_bfloat16* b = a2p + (size_t)n * KS2;
    *reinterpret_cast<__nv_bfloat162*>(b + c4) = h01;
    *reinterpret_cast<__nv_bfloat162*>(b + c4 + 2) = h23;
    *reinterpret_cast<__nv_bfloat162*>(b + HC1 + c4) = l01;
    *reinterpret_cast<__nv_bfloat162*>(b + HC1 + c4 + 2) = l23;
}

// ---------------- layer 2 fused softmax + aggregate + head-mean + bias ----------------
__global__ __launch_bounds__(256) void agg2_kernel(
    const float* __restrict__ h2, const float* __restrict__ asrc,
    const float* __restrict__ adst, const int* __restrict__ rowptr,
    const int* __restrict__ col, const float* __restrict__ bias,
    float* __restrict__ out)
{
    const int n = blockIdx.x;
    const int t = threadIdx.x;
    const int warp = t >> 5, lane = t & 31;
    __shared__ float sadst[8], sm[8], ss[8];
    __shared__ float red[8][8];
    __shared__ float salpha[32 * 8];
    __shared__ int scol[32];

    const int start = rowptr[n], end = rowptr[n + 1];
    if (t < 8) sadst[t] = adst[n * 8 + t];
    __syncthreads();

    float lm[8];
#pragma unroll
    for (int h = 0; h < 8; h++) lm[h] = -1e30f;
    for (int j = start + t; j < end; j += 256) {
        const float* ap = asrc + (size_t)col[j] * 8;
#pragma unroll
        for (int h = 0; h < 8; h++) {
            float e = ap[h] + sadst[h];
            e = e > 0.f ? e : NEG_SLOPE * e;
            lm[h] = fmaxf(lm[h], e);
        }
    }
#pragma unroll
    for (int h = 0; h < 8; h++)
#pragma unroll
        for (int off = 16; off > 0; off >>= 1)
            lm[h] = fmaxf(lm[h], __shfl_xor_sync(0xffffffffu, lm[h], off));
    if (lane == 0)
#pragma unroll
        for (int h = 0; h < 8; h++) red[warp][h] = lm[h];
    __syncthreads();
    if (t < 8) {
        float m = red[0][t];
#pragma unroll
        for (int w = 1; w < 8; w++) m = fmaxf(m, red[w][t]);
        sm[t] = m;
    }
    __syncthreads();

    float lsum[8];
#pragma unroll
    for (int h = 0; h < 8; h++) lsum[h] = 0.f;
    for (int j = start + t; j < end; j += 256) {
        const float* ap = asrc + (size_t)col[j] * 8;
#pragma unroll
        for (int h = 0; h < 8; h++) {
            float e = ap[h] + sadst[h];
            e = e > 0.f ? e : NEG_SLOPE * e;
            lsum[h] += expf(e - sm[h]);
        }
    }
#pragma unroll
    for (int h = 0; h < 8; h++)
#pragma unroll
        for (int off = 16; off > 0; off >>= 1)
            lsum[h] += __shfl_xor_sync(0xffffffffu, lsum[h], off);
    if (lane == 0)
#pragma unroll
        for (int h = 0; h < 8; h++) red[warp][h] = lsum[h];
    __syncthreads();
    if (t < 8) {
        float s = 0.f;
#pragma unroll
        for (int w = 0; w < 8; w++) s += red[w][t];
        ss[t] = s;
    }
    __syncthreads();

    float acc[8];
#pragma unroll
    for (int h = 0; h < 8; h++) acc[h] = 0.f;
    for (int base = start; base < end; base += 32) {
        int cnt = min(32, end - base);
        if (t < cnt) scol[t] = col[base + t];
        if (t < cnt * 8) {
            int j = base + (t >> 3);
            int h = t & 7;
            float e = asrc[(size_t)col[j] * 8 + h] + sadst[h];
            e = e > 0.f ? e : NEG_SLOPE * e;
            salpha[t] = expf(e - sm[h]) / ss[h];
        }
        __syncthreads();
        for (int q = 0; q < cnt; q++) {
            const float* hp = h2 + (size_t)scol[q] * HC2 + t;
#pragma unroll
            for (int h = 0; h < 8; h++)
                acc[h] = fmaf(salpha[q * 8 + h], hp[h * C2], acc[h]);
        }
        __syncthreads();
    }
    float s = 0.f;
#pragma unroll
    for (int h = 0; h < 8; h++) s += acc[h];
    out[(size_t)n * C2 + t] = 0.125f * s + bias[t];
}

// ---------------- host ----------------
extern "C" void kernel_launch(void* const* d_in, const int* in_sizes, int n_in,
                              void* d_out, int out_size)
{
    const float* x        = (const float*)d_in[0];
    const int*   src1     = (const int*)d_in[1];
    const int*   dst1     = (const int*)d_in[2];
    const int*   src2     = (const int*)d_in[3];
    const int*   dst2     = (const int*)d_in[4];
    const float* W1       = (const float*)d_in[5];
    const float* att_src1 = (const float*)d_in[6];
    const float* att_dst1 = (const float*)d_in[7];
    const float* b1       = (const float*)d_in[8];
    const float* W2       = (const float*)d_in[9];
    const float* att_src2 = (const float*)d_in[10];
    const float* att_dst2 = (const float*)d_in[11];
    const float* b2       = (const float*)d_in[12];
    float* out = (float*)d_out;

    const int E1 = in_sizes[1];
    const int E2 = in_sizes[3];

    float *h1, *h2, *as1, *ad1, *as2, *ad2;
    int *deg1, *rp1, *cur1, *col1, *deg2, *rp2, *cur2, *col2;
    __nv_bfloat16 *a1p, *b1p, *a2p, *b2p;
    cudaGetSymbolAddress((void**)&h1, g_h1);
    cudaGetSymbolAddress((void**)&h2, g_h2);
    cudaGetSymbolAddress((void**)&as1, g_as1);
    cudaGetSymbolAddress((void**)&ad1, g_ad1);
    cudaGetSymbolAddress((void**)&as2, g_as2);
    cudaGetSymbolAddress((void**)&ad2, g_ad2);
    cudaGetSymbolAddress((void**)&deg1, g_deg1);
    cudaGetSymbolAddress((void**)&rp1, g_rp1);
    cudaGetSymbolAddress((void**)&cur1, g_cur1);
    cudaGetSymbolAddress((void**)&col1, g_col1);
    cudaGetSymbolAddress((void**)&deg2, g_deg2);
    cudaGetSymbolAddress((void**)&rp2, g_rp2);
    cudaGetSymbolAddress((void**)&cur2, g_cur2);
    cudaGetSymbolAddress((void**)&col2, g_col2);
    cudaGetSymbolAddress((void**)&a1p, g_a1p);
    cudaGetSymbolAddress((void**)&b1p, g_b1p);
    cudaGetSymbolAddress((void**)&a2p, g_a2p);
    cudaGetSymbolAddress((void**)&b2p, g_b2p);

    cudaFuncSetAttribute(gemm_mma, cudaFuncAttributeMaxDynamicSharedMemorySize, SMEM_GEMM);

    // ---- layer 1 ----  (GEMM1 stays launch #4 for ncu capture)
    {
        size_t tot = (size_t)N0 * (D / 4);
        conv_split_kernel<<<(unsigned)((tot + 255) / 256), 256>>>(x, a1p, N0, D);       // 1
    }
    conv_wt_kernel<<<(D * HC1 + 255) / 256, 256>>>(W1, b1p, D, HC1);                     // 2
    zero2_kernel<<<(N0 * H1 + 255) / 256, 256>>>(as1, N0 * H1, ad1, N1 * H1);            // 3
    {
        dim3 grid(HC1 / 128, (N0 + 127) / 128);
        gemm_mma<<<grid, 256, SMEM_GEMM>>>(a1p, b1p, h1, N0, HC1, KS1,                   // 4 (profiled)
                                           att_src1, att_dst1, as1, ad1, C1, N1);
    }

    // ---- fused CSR build (both layers) ----
    zero_deg_kernel<<<(N1 + 255) / 256, 256>>>(deg1, N1, deg2, N2);
    hist2_kernel<<<(E1 + E2 + 255) / 256, 256>>>(dst1, E1, deg1, dst2, E2, deg2);
    scan2_kernel<<<2, 1024>>>(deg1, rp1, cur1, N1, deg2, rp2, cur2, N2);
    scatter2_kernel<<<(E1 + E2 + 255) / 256, 256>>>(src1, dst1, E1, cur1, col1,
                                                    src2, dst2, E2, cur2, col2);

    agg1_kernel<<<N1, 128>>>(h1, as1, ad1, rp1, col1, b1, a2p);

    // ---- layer 2 ----
    conv_wt_kernel<<<(HC1 * HC2 + 255) / 256, 256>>>(W2, b2p, HC1, HC2);
    zero2_kernel<<<(N1 * H2 + 255) / 256, 256>>>(as2, N1 * H2, ad2, N2 * H2);
    {
        dim3 grid(HC2 / 128, (N1 + 127) / 128);
        gemm_mma<<<grid, 256, SMEM_GEMM>>>(a2p, b2p, h2, N1, HC2, KS2,
                                           att_src2, att_dst2, as2, ad2, C2, N2);
    }

    agg2_kernel<<<N2, 256>>>(h2, as2, ad2, rp2, col2, b2, out);

    (void)n_in; (void)out_size;
}

// round 11
// speedup vs baseline: 1.6920x; 1.6594x over previous
#include <cuda_runtime.h>
#include <cuda_fp16.h>
#include <cstdint>
#include <math.h>

// ---------------- problem constants ----------------
#define N0 120000
#define N1 24000
#define N2 6000
#define D  256
#define H1 8
#define C1 64
#define HC1 (H1*C1)     // 512
#define H2 8
#define C2 256
#define HC2 (H2*C2)     // 2048
#define E1MAX 384000
#define E2MAX 96000
#define NEG_SLOPE 0.2f

// ---------------- scratch (static device globals; no allocation) ----------------
__device__ float g_h1[(size_t)N0 * HC1];     // 245.8 MB
__device__ float g_h2[(size_t)N1 * HC2];     // 196.6 MB
__device__ float g_as1[(size_t)N0 * H1];
__device__ float g_ad1[(size_t)N1 * H1];
__device__ float g_as2[(size_t)N1 * H2];
__device__ float g_ad2[(size_t)N2 * H2];
__device__ int g_deg1[N1];
__device__ int g_rp1[N1 + 1];
__device__ int g_cur1[N1];
__device__ int g_col1[E1MAX];
__device__ int g_deg2[N2];
__device__ int g_rp2[N2 + 1];
__device__ int g_cur2[N2];
__device__ int g_col2[E2MAX];
// fp16 single-precision GEMM operands
__device__ __half g_a1p[(size_t)N0 * D];     // 61.4 MB
__device__ __half g_b1p[(size_t)HC1 * D];    //  0.26 MB
__device__ __half g_a2p[(size_t)N1 * HC1];   // 24.6 MB
__device__ __half g_b2p[(size_t)HC2 * HC1];  //  2.1 MB

// ================= PTX helpers =================
__device__ __forceinline__ uint32_t smem_u32(const void* p) {
    uint32_t a;
    asm("{ .reg .u64 t; cvta.to.shared.u64 t, %1; cvt.u32.u64 %0, t; }" : "=r"(a) : "l"(p));
    return a;
}
#define CP_ASYNC16(sp, gp) \
    asm volatile("cp.async.cg.shared.global [%0], [%1], 16;" :: "r"(sp), "l"(gp) : "memory")
#define CP_COMMIT() asm volatile("cp.async.commit_group;" ::: "memory")
#define CP_WAIT(n)  asm volatile("cp.async.wait_group %0;" :: "n"(n) : "memory")
#define LDMX4(r, addr) \
    asm volatile("ldmatrix.sync.aligned.m8n8.x4.shared.b16 {%0,%1,%2,%3}, [%4];" \
        : "=r"((r)[0]), "=r"((r)[1]), "=r"((r)[2]), "=r"((r)[3]) : "r"(addr))
#define MMA16816(d, a, b0v, b1v) \
    asm volatile("mma.sync.aligned.m16n8k16.row.col.f32.f16.f16.f32 " \
        "{%0,%1,%2,%3}, {%4,%5,%6,%7}, {%8,%9}, {%0,%1,%2,%3};" \
        : "+f"((d)[0]), "+f"((d)[1]), "+f"((d)[2]), "+f"((d)[3]) \
        : "r"((a)[0]), "r"((a)[1]), "r"((a)[2]), "r"((a)[3]), "r"(b0v), "r"(b1v))

// ================= fp16 mma.sync GEMM + fused score epilogue ====
// A [M, K] fp16 row-major, B [Nfull, K] fp16 row-major (i.e. B^T K-major).
// CTA tile 128x128, BK=64 (128B rows, SW128), 3-stage cp.async, 2 CTAs/SM.
#define STAGE_BYTES 32768
#define SMEM_GEMM   (3 * STAGE_BYTES)

__device__ __forceinline__ void gemm_load_stage(
    const __half* __restrict__ A, const __half* __restrict__ B,
    int M, int K, int bm, int bn, int c, uint32_t stbase, int tid)
{
    const int r0 = tid >> 3;
    const int kseg = tid & 7;
    const uint32_t kb = (uint32_t)(kseg * 16);
    const uint32_t abase = stbase;
    const uint32_t bbase = stbase + 16384;
#pragma unroll
    for (int i = 0; i < 4; i++) {
        int row = r0 + i * 32;
        int grow = bm + row; if (grow >= M) grow = M - 1;
        const void* gp = (const void*)(A + (size_t)grow * K + c * 64 + kseg * 8);
        uint32_t sp = abase + (uint32_t)(row * 128) + (kb ^ (uint32_t)((row & 7) << 4));
        CP_ASYNC16(sp, gp);
    }
#pragma unroll
    for (int i = 0; i < 4; i++) {
        int row = r0 + i * 32;
        const void* gp = (const void*)(B + (size_t)(bn + row) * K + c * 64 + kseg * 8);
        uint32_t sp = bbase + (uint32_t)(row * 128) + (kb ^ (uint32_t)((row & 7) << 4));
        CP_ASYNC16(sp, gp);
    }
}

__global__ __launch_bounds__(256, 2) void gemm_mma(
    const __half* __restrict__ A, const __half* __restrict__ B,
    float* __restrict__ C, int M, int Nfull, int K,
    const float* __restrict__ attS, const float* __restrict__ attD,
    float* __restrict__ aS, float* __restrict__ aD, int Chead, int Ndst)
{
    extern __shared__ __align__(1024) char smem[];
    const uint32_t sb = smem_u32(smem);
    const int tid = threadIdx.x;
    const int lane = tid & 31, wid = tid >> 5;
    const int wm = wid & 3, wn = wid >> 2;
    const int bm = blockIdx.y * 128, bn = blockIdx.x * 128;

    int arow[2], asw[2];
#pragma unroll
    for (int mi = 0; mi < 2; mi++) {
        int r = wm * 32 + mi * 16 + (lane & 7) + ((lane >> 3) & 1) * 8;
        arow[mi] = r * 128;
        asw[mi] = (r & 7) << 4;
    }
    const uint32_t akadd = ((lane >> 4) & 1) * 16;
    int brow[4], bsw[4];
#pragma unroll
    for (int nb = 0; nb < 4; nb++) {
        int r = wn * 64 + nb * 16 + ((lane >> 4) & 1) * 8 + (lane & 7);
        brow[nb] = r * 128;
        bsw[nb] = (r & 7) << 4;
    }
    const uint32_t bkadd = ((lane >> 3) & 1) * 16;

    float acc[2][8][4];
#pragma unroll
    for (int mi = 0; mi < 2; mi++)
#pragma unroll
        for (int ni = 0; ni < 8; ni++)
#pragma unroll
            for (int q = 0; q < 4; q++) acc[mi][ni][q] = 0.f;

    const int nch = K >> 6;

    gemm_load_stage(A, B, M, K, bm, bn, 0, sb, tid); CP_COMMIT();
    gemm_load_stage(A, B, M, K, bm, bn, 1, sb + STAGE_BYTES, tid); CP_COMMIT();

    for (int c = 0; c < nch; c++) {
        if (c + 1 < nch) { CP_WAIT(1); } else { CP_WAIT(0); }
        __syncthreads();
        if (c + 2 < nch) {
            gemm_load_stage(A, B, M, K, bm, bn, c + 2, sb + ((c + 2) % 3) * STAGE_BYTES, tid);
            CP_COMMIT();
        }

        const uint32_t abase = sb + (c % 3) * STAGE_BYTES;
        const uint32_t bbase = abase + 16384;
#pragma unroll
        for (int ks = 0; ks < 4; ks++) {
            const uint32_t k0b = ks * 32;
            uint32_t af[2][4];
#pragma unroll
            for (int mi = 0; mi < 2; mi++) {
                uint32_t addr = abase + arow[mi] + ((k0b + akadd) ^ (uint32_t)asw[mi]);
                LDMX4(af[mi], addr);
            }
            uint32_t bf[4][4];
#pragma unroll
            for (int nb = 0; nb < 4; nb++) {
                uint32_t addr = bbase + brow[nb] + ((k0b + bkadd) ^ (uint32_t)bsw[nb]);
                LDMX4(bf[nb], addr);
            }
#pragma unroll
            for (int mi = 0; mi < 2; mi++)
#pragma unroll
                for (int ni = 0; ni < 8; ni++) {
                    const int nb = ni >> 1, hf = ni & 1;
                    MMA16816(acc[mi][ni], af[mi], bf[nb][hf * 2], bf[nb][hf * 2 + 1]);
                }
        }
    }
    __syncthreads();

    const int crow0 = bm + wm * 32 + (lane >> 2);
    const int ccol0 = bn + wn * 64 + (lane & 3) * 2;

    // ---- fused attention scores ----
    {
        const int head = (bn + wn * 64) / Chead;
        float psrc[2][2], pdst[2][2];
#pragma unroll
        for (int mi = 0; mi < 2; mi++)
#pragma unroll
            for (int hf = 0; hf < 2; hf++) { psrc[mi][hf] = 0.f; pdst[mi][hf] = 0.f; }
#pragma unroll
        for (int ni = 0; ni < 8; ni++) {
            int gc = ccol0 + ni * 8;
            float s0 = attS[gc], s1 = attS[gc + 1];
            float d0 = attD[gc], d1 = attD[gc + 1];
#pragma unroll
            for (int mi = 0; mi < 2; mi++)
#pragma unroll
                for (int hf = 0; hf < 2; hf++) {
                    psrc[mi][hf] = fmaf(acc[mi][ni][hf * 2], s0, fmaf(acc[mi][ni][hf * 2 + 1], s1, psrc[mi][hf]));
                    pdst[mi][hf] = fmaf(acc[mi][ni][hf * 2], d0, fmaf(acc[mi][ni][hf * 2 + 1], d1, pdst[mi][hf]));
                }
        }
#pragma unroll
        for (int mi = 0; mi < 2; mi++)
#pragma unroll
            for (int hf = 0; hf < 2; hf++) {
#pragma unroll
                for (int off = 1; off < 4; off <<= 1) {
                    psrc[mi][hf] += __shfl_xor_sync(0xffffffffu, psrc[mi][hf], off);
                    pdst[mi][hf] += __shfl_xor_sync(0xffffffffu, pdst[mi][hf], off);
                }
            }
        if ((lane & 3) == 0) {
#pragma unroll
            for (int mi = 0; mi < 2; mi++)
#pragma unroll
                for (int hf = 0; hf < 2; hf++) {
                    int row = crow0 + mi * 16 + hf * 8;
                    if (row < M) {
                        atomicAdd(&aS[(size_t)row * 8 + head], psrc[mi][hf]);
                        if (row < Ndst) atomicAdd(&aD[(size_t)row * 8 + head], pdst[mi][hf]);
                    }
                }
        }
    }

#pragma unroll
    for (int mi = 0; mi < 2; mi++)
#pragma unroll
        for (int hf = 0; hf < 2; hf++) {
            int row = crow0 + mi * 16 + hf * 8;
            if (row < M) {
                float* cp = C + (size_t)row * Nfull + ccol0;
#pragma unroll
                for (int ni = 0; ni < 8; ni++) {
                    float2 v = make_float2(acc[mi][ni][hf * 2], acc[mi][ni][hf * 2 + 1]);
                    *reinterpret_cast<float2*>(cp + ni * 8) = v;
                }
            }
        }
}

// ---------------- conversions ----------------
// X (M x K fp32) -> fp16 (M x K)
__global__ void conv_f16_kernel(const float* __restrict__ X, __half* __restrict__ Ap,
                                int M, int K)
{
    size_t i = (size_t)blockIdx.x * blockDim.x + threadIdx.x;
    size_t total = (size_t)M * (K >> 2);
    if (i >= total) return;
    float4 v = *reinterpret_cast<const float4*>(X + i * 4);
    __half2 h01, h23;
    h01 = __floats2half2_rn(v.x, v.y);
    h23 = __floats2half2_rn(v.z, v.w);
    *reinterpret_cast<__half2*>(Ap + i * 4) = h01;
    *reinterpret_cast<__half2*>(Ap + i * 4 + 2) = h23;
}
// W (K x N fp32) -> B (N x K fp16) transposed
__global__ void conv_wt_kernel(const float* __restrict__ W, __half* __restrict__ Bp,
                               int K, int N)
{
    int idx = blockIdx.x * blockDim.x + threadIdx.x;
    if (idx >= K * N) return;
    int k = idx % K;
    int n = idx / K;
    Bp[(size_t)n * K + k] = __float2half_rn(W[(size_t)k * N + n]);
}

__global__ void zero2_kernel(float* p0, int n0, float* p1, int n1) {
    int i = blockIdx.x * blockDim.x + threadIdx.x;
    if (i < n0) p0[i] = 0.f;
    if (i < n1) p1[i] = 0.f;
}

// ---------------- CSR build (both layers fused) ----------------
__global__ void zero_deg_kernel(int* d1, int n1, int* d2, int n2) {
    int i = blockIdx.x * blockDim.x + threadIdx.x;
    if (i < n1) d1[i] = 0;
    if (i < n2) d2[i] = 0;
}
__global__ void hist2_kernel(const int* __restrict__ dstA, int EA, int* __restrict__ degA,
                             const int* __restrict__ dstB, int EB, int* __restrict__ degB)
{
    int i = blockIdx.x * blockDim.x + threadIdx.x;
    if (i < EA) atomicAdd(&degA[dstA[i]], 1);
    else {
        int j = i - EA;
        if (j < EB) atomicAdd(&degB[dstB[j]], 1);
    }
}
__global__ __launch_bounds__(1024) void scan2_kernel(
    const int* __restrict__ degA, int* __restrict__ rpA, int* __restrict__ curA, int nA,
    const int* __restrict__ degB, int* __restrict__ rpB, int* __restrict__ curB, int nB)
{
    const int* deg = blockIdx.x ? degB : degA;
    int* rowptr = blockIdx.x ? rpB : rpA;
    int* cursor = blockIdx.x ? curB : curA;
    int n = blockIdx.x ? nB : nA;
    __shared__ int sh[1024];
    int t = threadIdx.x;
    int per = (n + 1023) >> 10;
    int lo = t * per;
    int hi = min(lo + per, n);
    int s = 0;
    for (int i = lo; i < hi; i++) s += deg[i];
    sh[t] = s;
    __syncthreads();
    for (int off = 1; off < 1024; off <<= 1) {
        int v = (t >= off) ? sh[t - off] : 0;
        __syncthreads();
        sh[t] += v;
        __syncthreads();
    }
    int run = (t == 0) ? 0 : sh[t - 1];
    for (int i = lo; i < hi; i++) {
        rowptr[i] = run;
        cursor[i] = run;
        run += deg[i];
    }
    if (t == 0) rowptr[n] = sh[1023];
}
__global__ void scatter2_kernel(const int* __restrict__ srcA, const int* __restrict__ dstA, int EA,
                                int* __restrict__ curA, int* __restrict__ colA,
                                const int* __restrict__ srcB, const int* __restrict__ dstB, int EB,
                                int* __restrict__ curB, int* __restrict__ colB)
{
    int i = blockIdx.x * blockDim.x + threadIdx.x;
    if (i < EA) {
        int p = atomicAdd(&curA[dstA[i]], 1);
        colA[p] = srcA[i];
    } else {
        int j = i - EA;
        if (j < EB) {
            int p = atomicAdd(&curB[dstB[j]], 1);
            colB[p] = srcB[j];
        }
    }
}

// ---------------- layer 1 fused softmax + aggregate + bias + ELU -> fp16 a2p ----------------
__global__ __launch_bounds__(128) void agg1_kernel(
    const float* __restrict__ h1, const float* __restrict__ asrc,
    const float* __restrict__ adst, const int* __restrict__ rowptr,
    const int* __restrict__ col, const float* __restrict__ bias,
    __half* __restrict__ a2p)
{
    const int n = blockIdx.x;
    const int t = threadIdx.x;
    const int warp = t >> 5, lane = t & 31;
    __shared__ float sadst[8], sm[8], ss[8];
    __shared__ float red[4][8];
    __shared__ float salpha[16 * 8];
    __shared__ int scol[16];

    const int start = rowptr[n], end = rowptr[n + 1];
    if (t < 8) sadst[t] = adst[n * 8 + t];
    __syncthreads();

    float lm[8];
#pragma unroll
    for (int h = 0; h < 8; h++) lm[h] = -1e30f;
    for (int j = start + t; j < end; j += 128) {
        const float* ap = asrc + (size_t)col[j] * 8;
#pragma unroll
        for (int h = 0; h < 8; h++) {
            float e = ap[h] + sadst[h];
            e = e > 0.f ? e : NEG_SLOPE * e;
            lm[h] = fmaxf(lm[h], e);
        }
    }
#pragma unroll
    for (int h = 0; h < 8; h++)
#pragma unroll
        for (int off = 16; off > 0; off >>= 1)
            lm[h] = fmaxf(lm[h], __shfl_xor_sync(0xffffffffu, lm[h], off));
    if (lane == 0)
#pragma unroll
        for (int h = 0; h < 8; h++) red[warp][h] = lm[h];
    __syncthreads();
    if (t < 8) sm[t] = fmaxf(fmaxf(red[0][t], red[1][t]), fmaxf(red[2][t], red[3][t]));
    __syncthreads();

    float lsum[8];
#pragma unroll
    for (int h = 0; h < 8; h++) lsum[h] = 0.f;
    for (int j = start + t; j < end; j += 128) {
        const float* ap = asrc + (size_t)col[j] * 8;
#pragma unroll
        for (int h = 0; h < 8; h++) {
            float e = ap[h] + sadst[h];
            e = e > 0.f ? e : NEG_SLOPE * e;
            lsum[h] += expf(e - sm[h]);
        }
    }
#pragma unroll
    for (int h = 0; h < 8; h++)
#pragma unroll
        for (int off = 16; off > 0; off >>= 1)
            lsum[h] += __shfl_xor_sync(0xffffffffu, lsum[h], off);
    if (lane == 0)
#pragma unroll
        for (int h = 0; h < 8; h++) red[warp][h] = lsum[h];
    __syncthreads();
    if (t < 8) ss[t] = red[0][t] + red[1][t] + red[2][t] + red[3][t];
    __syncthreads();

    float acc0 = 0.f, acc1 = 0.f, acc2 = 0.f, acc3 = 0.f;
    const int head = t >> 4;
    const int c4 = t << 2;
    for (int base = start; base < end; base += 16) {
        int cnt = min(16, end - base);
        if (t < cnt) scol[t] = col[base + t];
        if (t < cnt * 8) {
            int j = base + (t >> 3);
            int h = t & 7;
            float e = asrc[(size_t)col[j] * 8 + h] + sadst[h];
            e = e > 0.f ? e : NEG_SLOPE * e;
            salpha[t] = expf(e - sm[h]) / ss[h];
        }
        __syncthreads();
        for (int q = 0; q < cnt; q++) {
            int s = scol[q];
            float a = salpha[q * 8 + head];
            float4 v = *reinterpret_cast<const float4*>(h1 + (size_t)s * HC1 + c4);
            acc0 = fmaf(a, v.x, acc0);
            acc1 = fmaf(a, v.y, acc1);
            acc2 = fmaf(a, v.z, acc2);
            acc3 = fmaf(a, v.w, acc3);
        }
        __syncthreads();
    }
    // bias + ELU -> fp16 store
    float o[4] = {acc0, acc1, acc2, acc3};
#pragma unroll
    for (int i = 0; i < 4; i++) {
        float v = o[i] + bias[c4 + i];
        o[i] = v > 0.f ? v : expm1f(v);
    }
    __half2 p01 = __floats2half2_rn(o[0], o[1]);
    __half2 p23 = __floats2half2_rn(o[2], o[3]);
    __half* b = a2p + (size_t)n * HC1 + c4;
    *reinterpret_cast<__half2*>(b) = p01;
    *reinterpret_cast<__half2*>(b + 2) = p23;
}

// ---------------- layer 2 fused softmax + aggregate + head-mean + bias ----------------
__global__ __launch_bounds__(256) void agg2_kernel(
    const float* __restrict__ h2, const float* __restrict__ asrc,
    const float* __restrict__ adst, const int* __restrict__ rowptr,
    const int* __restrict__ col, const float* __restrict__ bias,
    float* __restrict__ out)
{
    const int n = blockIdx.x;
    const int t = threadIdx.x;
    const int warp = t >> 5, lane = t & 31;
    __shared__ float sadst[8], sm[8], ss[8];
    __shared__ float red[8][8];
    __shared__ float salpha[32 * 8];
    __shared__ int scol[32];

    const int start = rowptr[n], end = rowptr[n + 1];
    if (t < 8) sadst[t] = adst[n * 8 + t];
    __syncthreads();

    float lm[8];
#pragma unroll
    for (int h = 0; h < 8; h++) lm[h] = -1e30f;
    for (int j = start + t; j < end; j += 256) {
        const float* ap = asrc + (size_t)col[j] * 8;
#pragma unroll
        for (int h = 0; h < 8; h++) {
            float e = ap[h] + sadst[h];
            e = e > 0.f ? e : NEG_SLOPE * e;
            lm[h] = fmaxf(lm[h], e);
        }
    }
#pragma unroll
    for (int h = 0; h < 8; h++)
#pragma unroll
        for (int off = 16; off > 0; off >>= 1)
            lm[h] = fmaxf(lm[h], __shfl_xor_sync(0xffffffffu, lm[h], off));
    if (lane == 0)
#pragma unroll
        for (int h = 0; h < 8; h++) red[warp][h] = lm[h];
    __syncthreads();
    if (t < 8) {
        float m = red[0][t];
#pragma unroll
        for (int w = 1; w < 8; w++) m = fmaxf(m, red[w][t]);
        sm[t] = m;
    }
    __syncthreads();

    float lsum[8];
#pragma unroll
    for (int h = 0; h < 8; h++) lsum[h] = 0.f;
    for (int j = start + t; j < end; j += 256) {
        const float* ap = asrc + (size_t)col[j] * 8;
#pragma unroll
        for (int h = 0; h < 8; h++) {
            float e = ap[h] + sadst[h];
            e = e > 0.f ? e : NEG_SLOPE * e;
            lsum[h] += expf(e - sm[h]);
        }
    }
#pragma unroll
    for (int h = 0; h < 8; h++)
#pragma unroll
        for (int off = 16; off > 0; off >>= 1)
            lsum[h] += __shfl_xor_sync(0xffffffffu, lsum[h], off);
    if (lane == 0)
#pragma unroll
        for (int h = 0; h < 8; h++) red[warp][h] = lsum[h];
    __syncthreads();
    if (t < 8) {
        float s = 0.f;
#pragma unroll
        for (int w = 0; w < 8; w++) s += red[w][t];
        ss[t] = s;
    }
    __syncthreads();

    float acc[8];
#pragma unroll
    for (int h = 0; h < 8; h++) acc[h] = 0.f;
    for (int base = start; base < end; base += 32) {
        int cnt = min(32, end - base);
        if (t < cnt) scol[t] = col[base + t];
        if (t < cnt * 8) {
            int j = base + (t >> 3);
            int h = t & 7;
            float e = asrc[(size_t)col[j] * 8 + h] + sadst[h];
            e = e > 0.f ? e : NEG_SLOPE * e;
            salpha[t] = expf(e - sm[h]) / ss[h];
        }
        __syncthreads();
        for (int q = 0; q < cnt; q++) {
            const float* hp = h2 + (size_t)scol[q] * HC2 + t;
#pragma unroll
            for (int h = 0; h < 8; h++)
                acc[h] = fmaf(salpha[q * 8 + h], hp[h * C2], acc[h]);
        }
        __syncthreads();
    }
    float s = 0.f;
#pragma unroll
    for (int h = 0; h < 8; h++) s += acc[h];
    out[(size_t)n * C2 + t] = 0.125f * s + bias[t];
}

// ---------------- host ----------------
extern "C" void kernel_launch(void* const* d_in, const int* in_sizes, int n_in,
                              void* d_out, int out_size)
{
    const float* x        = (const float*)d_in[0];
    const int*   src1     = (const int*)d_in[1];
    const int*   dst1     = (const int*)d_in[2];
    const int*   src2     = (const int*)d_in[3];
    const int*   dst2     = (const int*)d_in[4];
    const float* W1       = (const float*)d_in[5];
    const float* att_src1 = (const float*)d_in[6];
    const float* att_dst1 = (const float*)d_in[7];
    const float* b1       = (const float*)d_in[8];
    const float* W2       = (const float*)d_in[9];
    const float* att_src2 = (const float*)d_in[10];
    const float* att_dst2 = (const float*)d_in[11];
    const float* b2       = (const float*)d_in[12];
    float* out = (float*)d_out;

    const int E1 = in_sizes[1];
    const int E2 = in_sizes[3];

    float *h1, *h2, *as1, *ad1, *as2, *ad2;
    int *deg1, *rp1, *cur1, *col1, *deg2, *rp2, *cur2, *col2;
    __half *a1p, *b1p, *a2p, *b2p;
    cudaGetSymbolAddress((void**)&h1, g_h1);
    cudaGetSymbolAddress((void**)&h2, g_h2);
    cudaGetSymbolAddress((void**)&as1, g_as1);
    cudaGetSymbolAddress((void**)&ad1, g_ad1);
    cudaGetSymbolAddress((void**)&as2, g_as2);
    cudaGetSymbolAddress((void**)&ad2, g_ad2);
    cudaGetSymbolAddress((void**)&deg1, g_deg1);
    cudaGetSymbolAddress((void**)&rp1, g_rp1);
    cudaGetSymbolAddress((void**)&cur1, g_cur1);
    cudaGetSymbolAddress((void**)&col1, g_col1);
    cudaGetSymbolAddress((void**)&deg2, g_deg2);
    cudaGetSymbolAddress((void**)&rp2, g_rp2);
    cudaGetSymbolAddress((void**)&cur2, g_cur2);
    cudaGetSymbolAddress((void**)&col2, g_col2);
    cudaGetSymbolAddress((void**)&a1p, g_a1p);
    cudaGetSymbolAddress((void**)&b1p, g_b1p);
    cudaGetSymbolAddress((void**)&a2p, g_a2p);
    cudaGetSymbolAddress((void**)&b2p, g_b2p);

    cudaFuncSetAttribute(gemm_mma, cudaFuncAttributeMaxDynamicSharedMemorySize, SMEM_GEMM);

    // ---- layer 1 ----  (GEMM1 stays launch #4 for ncu capture)
    {
        size_t tot = (size_t)N0 * (D / 4);
        conv_f16_kernel<<<(unsigned)((tot + 255) / 256), 256>>>(x, a1p, N0, D);          // 1
    }
    conv_wt_kernel<<<(D * HC1 + 255) / 256, 256>>>(W1, b1p, D, HC1);                     // 2
    zero2_kernel<<<(N0 * H1 + 255) / 256, 256>>>(as1, N0 * H1, ad1, N1 * H1);            // 3
    {
        dim3 grid(HC1 / 128, (N0 + 127) / 128);
        gemm_mma<<<grid, 256, SMEM_GEMM>>>(a1p, b1p, h1, N0, HC1, D,                     // 4 (profiled)
                                           att_src1, att_dst1, as1, ad1, C1, N1);
    }

    // ---- fused CSR build (both layers) ----
    zero_deg_kernel<<<(N1 + 255) / 256, 256>>>(deg1, N1, deg2, N2);
    hist2_kernel<<<(E1 + E2 + 255) / 256, 256>>>(dst1, E1, deg1, dst2, E2, deg2);
    scan2_kernel<<<2, 1024>>>(deg1, rp1, cur1, N1, deg2, rp2, cur2, N2);
    scatter2_kernel<<<(E1 + E2 + 255) / 256, 256>>>(src1, dst1, E1, cur1, col1,
                                                    src2, dst2, E2, cur2, col2);

    agg1_kernel<<<N1, 128>>>(h1, as1, ad1, rp1, col1, b1, a2p);

    // ---- layer 2 ----
    conv_wt_kernel<<<(HC1 * HC2 + 255) / 256, 256>>>(W2, b2p, HC1, HC2);
    zero2_kernel<<<(N1 * H2 + 255) / 256, 256>>>(as2, N1 * H2, ad2, N2 * H2);
    {
        dim3 grid(HC2 / 128, (N1 + 127) / 128);
        gemm_mma<<<grid, 256, SMEM_GEMM>>>(a2p, b2p, h2, N1, HC2, HC1,
                                           att_src2, att_dst2, as2, ad2, C2, N2);
    }

    agg2_kernel<<<N2, 256>>>(h2, as2, ad2, rp2, col2, b2, out);

    (void)n_in; (void)out_size;
}

// round 12
// speedup vs baseline: 1.8238x; 1.0779x over previous
#include <cuda_runtime.h>
#include <cuda_fp16.h>
#include <cstdint>
#include <math.h>

// ---------------- problem constants ----------------
#define N0 120000
#define N1 24000
#define N2 6000
#define D  256
#define H1 8
#define C1 64
#define HC1 (H1*C1)     // 512
#define H2 8
#define C2 256
#define HC2 (H2*C2)     // 2048
#define E1MAX 384000
#define E2MAX 96000
#define NEG_SLOPE 0.2f

// ---------------- scratch (static device globals; no allocation) ----------------
__device__ __half g_h1[(size_t)N0 * HC1];    // 122.9 MB (fp16)
__device__ __half g_h2[(size_t)N1 * HC2];    //  98.3 MB (fp16)
__device__ float g_as1[(size_t)N0 * H1];
__device__ float g_ad1[(size_t)N1 * H1];
__device__ float g_as2[(size_t)N1 * H2];
__device__ float g_ad2[(size_t)N2 * H2];
__device__ int g_deg1[N1];
__device__ int g_rp1[N1 + 1];
__device__ int g_cur1[N1];
__device__ int g_col1[E1MAX];
__device__ int g_deg2[N2];
__device__ int g_rp2[N2 + 1];
__device__ int g_cur2[N2];
__device__ int g_col2[E2MAX];
// fp16 GEMM operands
__device__ __half g_a1p[(size_t)N0 * D];     // 61.4 MB
__device__ __half g_b1p[(size_t)HC1 * D];    //  0.26 MB
__device__ __half g_a2p[(size_t)N1 * HC1];   // 24.6 MB
__device__ __half g_b2p[(size_t)HC2 * HC1];  //  2.1 MB

// ================= PTX helpers =================
__device__ __forceinline__ uint32_t smem_u32(const void* p) {
    uint32_t a;
    asm("{ .reg .u64 t; cvta.to.shared.u64 t, %1; cvt.u32.u64 %0, t; }" : "=r"(a) : "l"(p));
    return a;
}
#define CP_ASYNC16(sp, gp) \
    asm volatile("cp.async.cg.shared.global [%0], [%1], 16;" :: "r"(sp), "l"(gp) : "memory")
#define CP_COMMIT() asm volatile("cp.async.commit_group;" ::: "memory")
#define CP_WAIT(n)  asm volatile("cp.async.wait_group %0;" :: "n"(n) : "memory")
#define LDMX4(r, addr) \
    asm volatile("ldmatrix.sync.aligned.m8n8.x4.shared.b16 {%0,%1,%2,%3}, [%4];" \
        : "=r"((r)[0]), "=r"((r)[1]), "=r"((r)[2]), "=r"((r)[3]) : "r"(addr))
#define MMA16816(d, a, b0v, b1v) \
    asm volatile("mma.sync.aligned.m16n8k16.row.col.f32.f16.f16.f32 " \
        "{%0,%1,%2,%3}, {%4,%5,%6,%7}, {%8,%9}, {%0,%1,%2,%3};" \
        : "+f"((d)[0]), "+f"((d)[1]), "+f"((d)[2]), "+f"((d)[3]) \
        : "r"((a)[0]), "r"((a)[1]), "r"((a)[2]), "r"((a)[3]), "r"(b0v), "r"(b1v))

// ================= fp16 mma.sync GEMM + fused score epilogue, fp16 C ====
#define STAGE_BYTES 32768
#define SMEM_GEMM   (3 * STAGE_BYTES)

__device__ __forceinline__ void gemm_load_stage(
    const __half* __restrict__ A, const __half* __restrict__ B,
    int M, int K, int bm, int bn, int c, uint32_t stbase, int tid)
{
    const int r0 = tid >> 3;
    const int kseg = tid & 7;
    const uint32_t kb = (uint32_t)(kseg * 16);
    const uint32_t abase = stbase;
    const uint32_t bbase = stbase + 16384;
#pragma unroll
    for (int i = 0; i < 4; i++) {
        int row = r0 + i * 32;
        int grow = bm + row; if (grow >= M) grow = M - 1;
        const void* gp = (const void*)(A + (size_t)grow * K + c * 64 + kseg * 8);
        uint32_t sp = abase + (uint32_t)(row * 128) + (kb ^ (uint32_t)((row & 7) << 4));
        CP_ASYNC16(sp, gp);
    }
#pragma unroll
    for (int i = 0; i < 4; i++) {
        int row = r0 + i * 32;
        const void* gp = (const void*)(B + (size_t)(bn + row) * K + c * 64 + kseg * 8);
        uint32_t sp = bbase + (uint32_t)(row * 128) + (kb ^ (uint32_t)((row & 7) << 4));
        CP_ASYNC16(sp, gp);
    }
}

__global__ __launch_bounds__(256, 2) void gemm_mma(
    const __half* __restrict__ A, const __half* __restrict__ B,
    __half* __restrict__ C, int M, int Nfull, int K,
    const float* __restrict__ attS, const float* __restrict__ attD,
    float* __restrict__ aS, float* __restrict__ aD, int Chead, int Ndst)
{
    extern __shared__ __align__(1024) char smem[];
    const uint32_t sb = smem_u32(smem);
    const int tid = threadIdx.x;
    const int lane = tid & 31, wid = tid >> 5;
    const int wm = wid & 3, wn = wid >> 2;
    const int bm = blockIdx.y * 128, bn = blockIdx.x * 128;

    int arow[2], asw[2];
#pragma unroll
    for (int mi = 0; mi < 2; mi++) {
        int r = wm * 32 + mi * 16 + (lane & 7) + ((lane >> 3) & 1) * 8;
        arow[mi] = r * 128;
        asw[mi] = (r & 7) << 4;
    }
    const uint32_t akadd = ((lane >> 4) & 1) * 16;
    int brow[4], bsw[4];
#pragma unroll
    for (int nb = 0; nb < 4; nb++) {
        int r = wn * 64 + nb * 16 + ((lane >> 4) & 1) * 8 + (lane & 7);
        brow[nb] = r * 128;
        bsw[nb] = (r & 7) << 4;
    }
    const uint32_t bkadd = ((lane >> 3) & 1) * 16;

    float acc[2][8][4];
#pragma unroll
    for (int mi = 0; mi < 2; mi++)
#pragma unroll
        for (int ni = 0; ni < 8; ni++)
#pragma unroll
            for (int q = 0; q < 4; q++) acc[mi][ni][q] = 0.f;

    const int nch = K >> 6;

    gemm_load_stage(A, B, M, K, bm, bn, 0, sb, tid); CP_COMMIT();
    gemm_load_stage(A, B, M, K, bm, bn, 1, sb + STAGE_BYTES, tid); CP_COMMIT();

    for (int c = 0; c < nch; c++) {
        if (c + 1 < nch) { CP_WAIT(1); } else { CP_WAIT(0); }
        __syncthreads();
        if (c + 2 < nch) {
            gemm_load_stage(A, B, M, K, bm, bn, c + 2, sb + ((c + 2) % 3) * STAGE_BYTES, tid);
            CP_COMMIT();
        }

        const uint32_t abase = sb + (c % 3) * STAGE_BYTES;
        const uint32_t bbase = abase + 16384;
#pragma unroll
        for (int ks = 0; ks < 4; ks++) {
            const uint32_t k0b = ks * 32;
            uint32_t af[2][4];
#pragma unroll
            for (int mi = 0; mi < 2; mi++) {
                uint32_t addr = abase + arow[mi] + ((k0b + akadd) ^ (uint32_t)asw[mi]);
                LDMX4(af[mi], addr);
            }
            uint32_t bf[4][4];
#pragma unroll
            for (int nb = 0; nb < 4; nb++) {
                uint32_t addr = bbase + brow[nb] + ((k0b + bkadd) ^ (uint32_t)bsw[nb]);
                LDMX4(bf[nb], addr);
            }
#pragma unroll
            for (int mi = 0; mi < 2; mi++)
#pragma unroll
                for (int ni = 0; ni < 8; ni++) {
                    const int nb = ni >> 1, hf = ni & 1;
                    MMA16816(acc[mi][ni], af[mi], bf[nb][hf * 2], bf[nb][hf * 2 + 1]);
                }
        }
    }
    __syncthreads();

    const int crow0 = bm + wm * 32 + (lane >> 2);
    const int ccol0 = bn + wn * 64 + (lane & 3) * 2;

    // ---- fused attention scores (from fp32 accumulators) ----
    {
        const int head = (bn + wn * 64) / Chead;
        float psrc[2][2], pdst[2][2];
#pragma unroll
        for (int mi = 0; mi < 2; mi++)
#pragma unroll
            for (int hf = 0; hf < 2; hf++) { psrc[mi][hf] = 0.f; pdst[mi][hf] = 0.f; }
#pragma unroll
        for (int ni = 0; ni < 8; ni++) {
            int gc = ccol0 + ni * 8;
            float s0 = attS[gc], s1 = attS[gc + 1];
            float d0 = attD[gc], d1 = attD[gc + 1];
#pragma unroll
            for (int mi = 0; mi < 2; mi++)
#pragma unroll
                for (int hf = 0; hf < 2; hf++) {
                    psrc[mi][hf] = fmaf(acc[mi][ni][hf * 2], s0, fmaf(acc[mi][ni][hf * 2 + 1], s1, psrc[mi][hf]));
                    pdst[mi][hf] = fmaf(acc[mi][ni][hf * 2], d0, fmaf(acc[mi][ni][hf * 2 + 1], d1, pdst[mi][hf]));
                }
        }
#pragma unroll
        for (int mi = 0; mi < 2; mi++)
#pragma unroll
            for (int hf = 0; hf < 2; hf++) {
#pragma unroll
                for (int off = 1; off < 4; off <<= 1) {
                    psrc[mi][hf] += __shfl_xor_sync(0xffffffffu, psrc[mi][hf], off);
                    pdst[mi][hf] += __shfl_xor_sync(0xffffffffu, pdst[mi][hf], off);
                }
            }
        if ((lane & 3) == 0) {
#pragma unroll
            for (int mi = 0; mi < 2; mi++)
#pragma unroll
                for (int hf = 0; hf < 2; hf++) {
                    int row = crow0 + mi * 16 + hf * 8;
                    if (row < M) {
                        atomicAdd(&aS[(size_t)row * 8 + head], psrc[mi][hf]);
                        if (row < Ndst) atomicAdd(&aD[(size_t)row * 8 + head], pdst[mi][hf]);
                    }
                }
        }
    }

    // ---- store C as fp16 ----
#pragma unroll
    for (int mi = 0; mi < 2; mi++)
#pragma unroll
        for (int hf = 0; hf < 2; hf++) {
            int row = crow0 + mi * 16 + hf * 8;
            if (row < M) {
                __half* cp = C + (size_t)row * Nfull + ccol0;
#pragma unroll
                for (int ni = 0; ni < 8; ni++) {
                    __half2 v = __floats2half2_rn(acc[mi][ni][hf * 2], acc[mi][ni][hf * 2 + 1]);
                    *reinterpret_cast<__half2*>(cp + ni * 8) = v;
                }
            }
        }
}

// ---------------- conversions ----------------
__global__ void conv_f16_kernel(const float* __restrict__ X, __half* __restrict__ Ap,
                                int M, int K)
{
    size_t i = (size_t)blockIdx.x * blockDim.x + threadIdx.x;
    size_t total = (size_t)M * (K >> 2);
    if (i >= total) return;
    float4 v = *reinterpret_cast<const float4*>(X + i * 4);
    *reinterpret_cast<__half2*>(Ap + i * 4)     = __floats2half2_rn(v.x, v.y);
    *reinterpret_cast<__half2*>(Ap + i * 4 + 2) = __floats2half2_rn(v.z, v.w);
}
__global__ void conv_wt_kernel(const float* __restrict__ W, __half* __restrict__ Bp,
                               int K, int N)
{
    int idx = blockIdx.x * blockDim.x + threadIdx.x;
    if (idx >= K * N) return;
    int k = idx % K;
    int n = idx / K;
    Bp[(size_t)n * K + k] = __float2half_rn(W[(size_t)k * N + n]);
}

__global__ void zero2_kernel(float* p0, int n0, float* p1, int n1) {
    int i = blockIdx.x * blockDim.x + threadIdx.x;
    if (i < n0) p0[i] = 0.f;
    if (i < n1) p1[i] = 0.f;
}

// ---------------- CSR build (both layers fused) ----------------
__global__ void zero_deg_kernel(int* d1, int n1, int* d2, int n2) {
    int i = blockIdx.x * blockDim.x + threadIdx.x;
    if (i < n1) d1[i] = 0;
    if (i < n2) d2[i] = 0;
}
__global__ void hist2_kernel(const int* __restrict__ dstA, int EA, int* __restrict__ degA,
                             const int* __restrict__ dstB, int EB, int* __restrict__ degB)
{
    int i = blockIdx.x * blockDim.x + threadIdx.x;
    if (i < EA) atomicAdd(&degA[dstA[i]], 1);
    else {
        int j = i - EA;
        if (j < EB) atomicAdd(&degB[dstB[j]], 1);
    }
}
__global__ __launch_bounds__(1024) void scan2_kernel(
    const int* __restrict__ degA, int* __restrict__ rpA, int* __restrict__ curA, int nA,
    const int* __restrict__ degB, int* __restrict__ rpB, int* __restrict__ curB, int nB)
{
    const int* deg = blockIdx.x ? degB : degA;
    int* rowptr = blockIdx.x ? rpB : rpA;
    int* cursor = blockIdx.x ? curB : curA;
    int n = blockIdx.x ? nB : nA;
    __shared__ int sh[1024];
    int t = threadIdx.x;
    int per = (n + 1023) >> 10;
    int lo = t * per;
    int hi = min(lo + per, n);
    int s = 0;
    for (int i = lo; i < hi; i++) s += deg[i];
    sh[t] = s;
    __syncthreads();
    for (int off = 1; off < 1024; off <<= 1) {
        int v = (t >= off) ? sh[t - off] : 0;
        __syncthreads();
        sh[t] += v;
        __syncthreads();
    }
    int run = (t == 0) ? 0 : sh[t - 1];
    for (int i = lo; i < hi; i++) {
        rowptr[i] = run;
        cursor[i] = run;
        run += deg[i];
    }
    if (t == 0) rowptr[n] = sh[1023];
}
__global__ void scatter2_kernel(const int* __restrict__ srcA, const int* __restrict__ dstA, int EA,
                                int* __restrict__ curA, int* __restrict__ colA,
                                const int* __restrict__ srcB, const int* __restrict__ dstB, int EB,
                                int* __restrict__ curB, int* __restrict__ colB)
{
    int i = blockIdx.x * blockDim.x + threadIdx.x;
    if (i < EA) {
        int p = atomicAdd(&curA[dstA[i]], 1);
        colA[p] = srcA[i];
    } else {
        int j = i - EA;
        if (j < EB) {
            int p = atomicAdd(&curB[dstB[j]], 1);
            colB[p] = srcB[j];
        }
    }
}

// ---------------- layer 1 fused softmax + aggregate + bias + ELU -> fp16 a2p ----------------
__global__ __launch_bounds__(128) void agg1_kernel(
    const __half* __restrict__ h1, const float* __restrict__ asrc,
    const float* __restrict__ adst, const int* __restrict__ rowptr,
    const int* __restrict__ col, const float* __restrict__ bias,
    __half* __restrict__ a2p)
{
    const int n = blockIdx.x;
    const int t = threadIdx.x;
    const int warp = t >> 5, lane = t & 31;
    __shared__ float sadst[8], sm[8], ss[8];
    __shared__ float red[4][8];
    __shared__ float salpha[16 * 8];
    __shared__ int scol[16];

    const int start = rowptr[n], end = rowptr[n + 1];
    if (t < 8) sadst[t] = adst[n * 8 + t];
    __syncthreads();

    float lm[8];
#pragma unroll
    for (int h = 0; h < 8; h++) lm[h] = -1e30f;
    for (int j = start + t; j < end; j += 128) {
        const float* ap = asrc + (size_t)col[j] * 8;
#pragma unroll
        for (int h = 0; h < 8; h++) {
            float e = ap[h] + sadst[h];
            e = e > 0.f ? e : NEG_SLOPE * e;
            lm[h] = fmaxf(lm[h], e);
        }
    }
#pragma unroll
    for (int h = 0; h < 8; h++)
#pragma unroll
        for (int off = 16; off > 0; off >>= 1)
            lm[h] = fmaxf(lm[h], __shfl_xor_sync(0xffffffffu, lm[h], off));
    if (lane == 0)
#pragma unroll
        for (int h = 0; h < 8; h++) red[warp][h] = lm[h];
    __syncthreads();
    if (t < 8) sm[t] = fmaxf(fmaxf(red[0][t], red[1][t]), fmaxf(red[2][t], red[3][t]));
    __syncthreads();

    float lsum[8];
#pragma unroll
    for (int h = 0; h < 8; h++) lsum[h] = 0.f;
    for (int j = start + t; j < end; j += 128) {
        const float* ap = asrc + (size_t)col[j] * 8;
#pragma unroll
        for (int h = 0; h < 8; h++) {
            float e = ap[h] + sadst[h];
            e = e > 0.f ? e : NEG_SLOPE * e;
            lsum[h] += expf(e - sm[h]);
        }
    }
#pragma unroll
    for (int h = 0; h < 8; h++)
#pragma unroll
        for (int off = 16; off > 0; off >>= 1)
            lsum[h] += __shfl_xor_sync(0xffffffffu, lsum[h], off);
    if (lane == 0)
#pragma unroll
        for (int h = 0; h < 8; h++) red[warp][h] = lsum[h];
    __syncthreads();
    if (t < 8) ss[t] = red[0][t] + red[1][t] + red[2][t] + red[3][t];
    __syncthreads();

    float acc0 = 0.f, acc1 = 0.f, acc2 = 0.f, acc3 = 0.f;
    const int head = t >> 4;
    const int c4 = t << 2;
    for (int base = start; base < end; base += 16) {
        int cnt = min(16, end - base);
        if (t < cnt) scol[t] = col[base + t];
        if (t < cnt * 8) {
            int j = base + (t >> 3);
            int h = t & 7;
            float e = asrc[(size_t)col[j] * 8 + h] + sadst[h];
            e = e > 0.f ? e : NEG_SLOPE * e;
            salpha[t] = expf(e - sm[h]) / ss[h];
        }
        __syncthreads();
        for (int q = 0; q < cnt; q++) {
            int s = scol[q];
            float a = salpha[q * 8 + head];
            const __half2* hp = reinterpret_cast<const __half2*>(h1 + (size_t)s * HC1 + c4);
            float2 v01 = __half22float2(hp[0]);
            float2 v23 = __half22float2(hp[1]);
            acc0 = fmaf(a, v01.x, acc0);
            acc1 = fmaf(a, v01.y, acc1);
            acc2 = fmaf(a, v23.x, acc2);
            acc3 = fmaf(a, v23.y, acc3);
        }
        __syncthreads();
    }
    // bias + ELU -> fp16 store
    float o[4] = {acc0, acc1, acc2, acc3};
#pragma unroll
    for (int i = 0; i < 4; i++) {
        float v = o[i] + bias[c4 + i];
        o[i] = v > 0.f ? v : expm1f(v);
    }
    __half* b = a2p + (size_t)n * HC1 + c4;
    *reinterpret_cast<__half2*>(b)     = __floats2half2_rn(o[0], o[1]);
    *reinterpret_cast<__half2*>(b + 2) = __floats2half2_rn(o[2], o[3]);
}

// ---------------- layer 2 fused softmax + aggregate + head-mean + bias ----------------
__global__ __launch_bounds__(256) void agg2_kernel(
    const __half* __restrict__ h2, const float* __restrict__ asrc,
    const float* __restrict__ adst, const int* __restrict__ rowptr,
    const int* __restrict__ col, const float* __restrict__ bias,
    float* __restrict__ out)
{
    const int n = blockIdx.x;
    const int t = threadIdx.x;
    const int warp = t >> 5, lane = t & 31;
    __shared__ float sadst[8], sm[8], ss[8];
    __shared__ float red[8][8];
    __shared__ float salpha[32 * 8];
    __shared__ int scol[32];

    const int start = rowptr[n], end = rowptr[n + 1];
    if (t < 8) sadst[t] = adst[n * 8 + t];
    __syncthreads();

    float lm[8];
#pragma unroll
    for (int h = 0; h < 8; h++) lm[h] = -1e30f;
    for (int j = start + t; j < end; j += 256) {
        const float* ap = asrc + (size_t)col[j] * 8;
#pragma unroll
        for (int h = 0; h < 8; h++) {
            float e = ap[h] + sadst[h];
            e = e > 0.f ? e : NEG_SLOPE * e;
            lm[h] = fmaxf(lm[h], e);
        }
    }
#pragma unroll
    for (int h = 0; h < 8; h++)
#pragma unroll
        for (int off = 16; off > 0; off >>= 1)
            lm[h] = fmaxf(lm[h], __shfl_xor_sync(0xffffffffu, lm[h], off));
    if (lane == 0)
#pragma unroll
        for (int h = 0; h < 8; h++) red[warp][h] = lm[h];
    __syncthreads();
    if (t < 8) {
        float m = red[0][t];
#pragma unroll
        for (int w = 1; w < 8; w++) m = fmaxf(m, red[w][t]);
        sm[t] = m;
    }
    __syncthreads();

    float lsum[8];
#pragma unroll
    for (int h = 0; h < 8; h++) lsum[h] = 0.f;
    for (int j = start + t; j < end; j += 256) {
        const float* ap = asrc + (size_t)col[j] * 8;
#pragma unroll
        for (int h = 0; h < 8; h++) {
            float e = ap[h] + sadst[h];
            e = e > 0.f ? e : NEG_SLOPE * e;
            lsum[h] += expf(e - sm[h]);
        }
    }
#pragma unroll
    for (int h = 0; h < 8; h++)
#pragma unroll
        for (int off = 16; off > 0; off >>= 1)
            lsum[h] += __shfl_xor_sync(0xffffffffu, lsum[h], off);
    if (lane == 0)
#pragma unroll
        for (int h = 0; h < 8; h++) red[warp][h] = lsum[h];
    __syncthreads();
    if (t < 8) {
        float s = 0.f;
#pragma unroll
        for (int w = 0; w < 8; w++) s += red[w][t];
        ss[t] = s;
    }
    __syncthreads();

    float acc[8];
#pragma unroll
    for (int h = 0; h < 8; h++) acc[h] = 0.f;
    for (int base = start; base < end; base += 32) {
        int cnt = min(32, end - base);
        if (t < cnt) scol[t] = col[base + t];
        if (t < cnt * 8) {
            int j = base + (t >> 3);
            int h = t & 7;
            float e = asrc[(size_t)col[j] * 8 + h] + sadst[h];
            e = e > 0.f ? e : NEG_SLOPE * e;
            salpha[t] = expf(e - sm[h]) / ss[h];
        }
        __syncthreads();
        for (int q = 0; q < cnt; q++) {
            const __half* hp = h2 + (size_t)scol[q] * HC2 + t;
#pragma unroll
            for (int h = 0; h < 8; h++)
                acc[h] = fmaf(salpha[q * 8 + h], __half2float(hp[h * C2]), acc[h]);
        }
        __syncthreads();
    }
    float s = 0.f;
#pragma unroll
    for (int h = 0; h < 8; h++) s += acc[h];
    out[(size_t)n * C2 + t] = 0.125f * s + bias[t];
}

// ---------------- host ----------------
extern "C" void kernel_launch(void* const* d_in, const int* in_sizes, int n_in,
                              void* d_out, int out_size)
{
    const float* x        = (const float*)d_in[0];
    const int*   src1     = (const int*)d_in[1];
    const int*   dst1     = (const int*)d_in[2];
    const int*   src2     = (const int*)d_in[3];
    const int*   dst2     = (const int*)d_in[4];
    const float* W1       = (const float*)d_in[5];
    const float* att_src1 = (const float*)d_in[6];
    const float* att_dst1 = (const float*)d_in[7];
    const float* b1       = (const float*)d_in[8];
    const float* W2       = (const float*)d_in[9];
    const float* att_src2 = (const float*)d_in[10];
    const float* att_dst2 = (const float*)d_in[11];
    const float* b2       = (const float*)d_in[12];
    float* out = (float*)d_out;

    const int E1 = in_sizes[1];
    const int E2 = in_sizes[3];

    float *as1, *ad1, *as2, *ad2;
    int *deg1, *rp1, *cur1, *col1, *deg2, *rp2, *cur2, *col2;
    __half *h1, *h2, *a1p, *b1p, *a2p, *b2p;
    cudaGetSymbolAddress((void**)&h1, g_h1);
    cudaGetSymbolAddress((void**)&h2, g_h2);
    cudaGetSymbolAddress((void**)&as1, g_as1);
    cudaGetSymbolAddress((void**)&ad1, g_ad1);
    cudaGetSymbolAddress((void**)&as2, g_as2);
    cudaGetSymbolAddress((void**)&ad2, g_ad2);
    cudaGetSymbolAddress((void**)&deg1, g_deg1);
    cudaGetSymbolAddress((void**)&rp1, g_rp1);
    cudaGetSymbolAddress((void**)&cur1, g_cur1);
    cudaGetSymbolAddress((void**)&col1, g_col1);
    cudaGetSymbolAddress((void**)&deg2, g_deg2);
    cudaGetSymbolAddress((void**)&rp2, g_rp2);
    cudaGetSymbolAddress((void**)&cur2, g_cur2);
    cudaGetSymbolAddress((void**)&col2, g_col2);
    cudaGetSymbolAddress((void**)&a1p, g_a1p);
    cudaGetSymbolAddress((void**)&b1p, g_b1p);
    cudaGetSymbolAddress((void**)&a2p, g_a2p);
    cudaGetSymbolAddress((void**)&b2p, g_b2p);

    cudaFuncSetAttribute(gemm_mma, cudaFuncAttributeMaxDynamicSharedMemorySize, SMEM_GEMM);

    // ---- layer 1 ----  (GEMM1 stays launch #4 for ncu capture)
    {
        size_t tot = (size_t)N0 * (D / 4);
        conv_f16_kernel<<<(unsigned)((tot + 255) / 256), 256>>>(x, a1p, N0, D);          // 1
    }
    conv_wt_kernel<<<(D * HC1 + 255) / 256, 256>>>(W1, b1p, D, HC1);                     // 2
    zero2_kernel<<<(N0 * H1 + 255) / 256, 256>>>(as1, N0 * H1, ad1, N1 * H1);            // 3
    {
        dim3 grid(HC1 / 128, (N0 + 127) / 128);
        gemm_mma<<<grid, 256, SMEM_GEMM>>>(a1p, b1p, h1, N0, HC1, D,                     // 4 (profiled)
                                           att_src1, att_dst1, as1, ad1, C1, N1);
    }

    // ---- fused CSR build (both layers) ----
    zero_deg_kernel<<<(N1 + 255) / 256, 256>>>(deg1, N1, deg2, N2);
    hist2_kernel<<<(E1 + E2 + 255) / 256, 256>>>(dst1, E1, deg1, dst2, E2, deg2);
    scan2_kernel<<<2, 1024>>>(deg1, rp1, cur1, N1, deg2, rp2, cur2, N2);
    scatter2_kernel<<<(E1 + E2 + 255) / 256, 256>>>(src1, dst1, E1, cur1, col1,
                                                    src2, dst2, E2, cur2, col2);

    agg1_kernel<<<N1, 128>>>(h1, as1, ad1, rp1, col1, b1, a2p);

    // ---- layer 2 ----
    conv_wt_kernel<<<(HC1 * HC2 + 255) / 256, 256>>>(W2, b2p, HC1, HC2);
    zero2_kernel<<<(N1 * H2 + 255) / 256, 256>>>(as2, N1 * H2, ad2, N2 * H2);
    {
        dim3 grid(HC2 / 128, (N1 + 127) / 128);
        gemm_mma<<<grid, 256, SMEM_GEMM>>>(a2p, b2p, h2, N1, HC2, HC1,
                                           att_src2, att_dst2, as2, ad2, C2, N2);
    }

    agg2_kernel<<<N2, 256>>>(h2, as2, ad2, rp2, col2, b2, out);

    (void)n_in; (void)out_size;
}

// round 13
// speedup vs baseline: 1.9296x; 1.0580x over previous
#include <cuda_runtime.h>
#include <cuda_fp16.h>
#include <cstdint>
#include <math.h>

// ---------------- problem constants ----------------
#define N0 120000
#define N1 24000
#define N2 6000
#define D  256
#define H1 8
#define C1 64
#define HC1 (H1*C1)     // 512
#define H2 8
#define C2 256
#define HC2 (H2*C2)     // 2048
#define E1MAX 384000
#define E2MAX 96000
#define NEG_SLOPE 0.2f

// ---------------- scratch (static device globals; no allocation) ----------------
__device__ __half g_h1[(size_t)N0 * HC1];    // 122.9 MB (fp16)
__device__ __half g_h2[(size_t)N1 * HC2];    //  98.3 MB (fp16)
__device__ float g_as1[(size_t)N0 * H1];
__device__ float g_ad1[(size_t)N1 * H1];
__device__ float g_as2[(size_t)N1 * H2];
__device__ float g_ad2[(size_t)N2 * H2];
__device__ int g_deg1[N1];
__device__ int g_rp1[N1 + 1];
__device__ int g_cur1[N1];
__device__ int g_col1[E1MAX];
__device__ int g_deg2[N2];
__device__ int g_rp2[N2 + 1];
__device__ int g_cur2[N2];
__device__ int g_col2[E2MAX];
// fp16 GEMM operands
__device__ __half g_a1p[(size_t)N0 * D];     // 61.4 MB
__device__ __half g_b1p[(size_t)HC1 * D];    //  0.26 MB
__device__ __half g_a2p[(size_t)N1 * HC1];   // 24.6 MB
__device__ __half g_b2p[(size_t)HC2 * HC1];  //  2.1 MB

// ================= PTX helpers =================
__device__ __forceinline__ uint32_t smem_u32(const void* p) {
    uint32_t a;
    asm("{ .reg .u64 t; cvta.to.shared.u64 t, %1; cvt.u32.u64 %0, t; }" : "=r"(a) : "l"(p));
    return a;
}
#define CP_ASYNC16(sp, gp) \
    asm volatile("cp.async.cg.shared.global [%0], [%1], 16;" :: "r"(sp), "l"(gp) : "memory")
#define CP_COMMIT() asm volatile("cp.async.commit_group;" ::: "memory")
#define CP_WAIT(n)  asm volatile("cp.async.wait_group %0;" :: "n"(n) : "memory")
#define LDMX4(r, addr) \
    asm volatile("ldmatrix.sync.aligned.m8n8.x4.shared.b16 {%0,%1,%2,%3}, [%4];" \
        : "=r"((r)[0]), "=r"((r)[1]), "=r"((r)[2]), "=r"((r)[3]) : "r"(addr))
#define MMA16816(d, a, b0v, b1v) \
    asm volatile("mma.sync.aligned.m16n8k16.row.col.f32.f16.f16.f32 " \
        "{%0,%1,%2,%3}, {%4,%5,%6,%7}, {%8,%9}, {%0,%1,%2,%3};" \
        : "+f"((d)[0]), "+f"((d)[1]), "+f"((d)[2]), "+f"((d)[3]) \
        : "r"((a)[0]), "r"((a)[1]), "r"((a)[2]), "r"((a)[3]), "r"(b0v), "r"(b1v))

// ================= fp16 mma.sync GEMM + fused score epilogue, fp16 C ====
#define STAGE_BYTES 32768
#define SMEM_GEMM   (3 * STAGE_BYTES)

__device__ __forceinline__ void gemm_load_stage(
    const __half* __restrict__ A, const __half* __restrict__ B,
    int M, int K, int bm, int bn, int c, uint32_t stbase, int tid)
{
    const int r0 = tid >> 3;
    const int kseg = tid & 7;
    const uint32_t kb = (uint32_t)(kseg * 16);
    const uint32_t abase = stbase;
    const uint32_t bbase = stbase + 16384;
#pragma unroll
    for (int i = 0; i < 4; i++) {
        int row = r0 + i * 32;
        int grow = bm + row; if (grow >= M) grow = M - 1;
        const void* gp = (const void*)(A + (size_t)grow * K + c * 64 + kseg * 8);
        uint32_t sp = abase + (uint32_t)(row * 128) + (kb ^ (uint32_t)((row & 7) << 4));
        CP_ASYNC16(sp, gp);
    }
#pragma unroll
    for (int i = 0; i < 4; i++) {
        int row = r0 + i * 32;
        const void* gp = (const void*)(B + (size_t)(bn + row) * K + c * 64 + kseg * 8);
        uint32_t sp = bbase + (uint32_t)(row * 128) + (kb ^ (uint32_t)((row & 7) << 4));
        CP_ASYNC16(sp, gp);
    }
}

__global__ __launch_bounds__(256, 2) void gemm_mma(
    const __half* __restrict__ A, const __half* __restrict__ B,
    __half* __restrict__ C, int M, int Nfull, int K,
    const float* __restrict__ attS, const float* __restrict__ attD,
    float* __restrict__ aS, float* __restrict__ aD, int Chead, int Ndst)
{
    extern __shared__ __align__(1024) char smem[];
    const uint32_t sb = smem_u32(smem);
    const int tid = threadIdx.x;
    const int lane = tid & 31, wid = tid >> 5;
    const int wm = wid & 3, wn = wid >> 2;
    const int bm = blockIdx.y * 128, bn = blockIdx.x * 128;

    int arow[2], asw[2];
#pragma unroll
    for (int mi = 0; mi < 2; mi++) {
        int r = wm * 32 + mi * 16 + (lane & 7) + ((lane >> 3) & 1) * 8;
        arow[mi] = r * 128;
        asw[mi] = (r & 7) << 4;
    }
    const uint32_t akadd = ((lane >> 4) & 1) * 16;
    int brow[4], bsw[4];
#pragma unroll
    for (int nb = 0; nb < 4; nb++) {
        int r = wn * 64 + nb * 16 + ((lane >> 4) & 1) * 8 + (lane & 7);
        brow[nb] = r * 128;
        bsw[nb] = (r & 7) << 4;
    }
    const uint32_t bkadd = ((lane >> 3) & 1) * 16;

    float acc[2][8][4];
#pragma unroll
    for (int mi = 0; mi < 2; mi++)
#pragma unroll
        for (int ni = 0; ni < 8; ni++)
#pragma unroll
            for (int q = 0; q < 4; q++) acc[mi][ni][q] = 0.f;

    const int nch = K >> 6;

    gemm_load_stage(A, B, M, K, bm, bn, 0, sb, tid); CP_COMMIT();
    gemm_load_stage(A, B, M, K, bm, bn, 1, sb + STAGE_BYTES, tid); CP_COMMIT();

    for (int c = 0; c < nch; c++) {
        if (c + 1 < nch) { CP_WAIT(1); } else { CP_WAIT(0); }
        __syncthreads();
        if (c + 2 < nch) {
            gemm_load_stage(A, B, M, K, bm, bn, c + 2, sb + ((c + 2) % 3) * STAGE_BYTES, tid);
            CP_COMMIT();
        }

        const uint32_t abase = sb + (c % 3) * STAGE_BYTES;
        const uint32_t bbase = abase + 16384;
#pragma unroll
        for (int ks = 0; ks < 4; ks++) {
            const uint32_t k0b = ks * 32;
            uint32_t af[2][4];
#pragma unroll
            for (int mi = 0; mi < 2; mi++) {
                uint32_t addr = abase + arow[mi] + ((k0b + akadd) ^ (uint32_t)asw[mi]);
                LDMX4(af[mi], addr);
            }
            uint32_t bf[4][4];
#pragma unroll
            for (int nb = 0; nb < 4; nb++) {
                uint32_t addr = bbase + brow[nb] + ((k0b + bkadd) ^ (uint32_t)bsw[nb]);
                LDMX4(bf[nb], addr);
            }
#pragma unroll
            for (int mi = 0; mi < 2; mi++)
#pragma unroll
                for (int ni = 0; ni < 8; ni++) {
                    const int nb = ni >> 1, hf = ni & 1;
                    MMA16816(acc[mi][ni], af[mi], bf[nb][hf * 2], bf[nb][hf * 2 + 1]);
                }
        }
    }
    __syncthreads();

    const int crow0 = bm + wm * 32 + (lane >> 2);
    const int ccol0 = bn + wn * 64 + (lane & 3) * 2;

    // ---- fused attention scores (from fp32 accumulators) ----
    {
        const int head = (bn + wn * 64) / Chead;
        float psrc[2][2], pdst[2][2];
#pragma unroll
        for (int mi = 0; mi < 2; mi++)
#pragma unroll
            for (int hf = 0; hf < 2; hf++) { psrc[mi][hf] = 0.f; pdst[mi][hf] = 0.f; }
#pragma unroll
        for (int ni = 0; ni < 8; ni++) {
            int gc = ccol0 + ni * 8;
            float s0 = attS[gc], s1 = attS[gc + 1];
            float d0 = attD[gc], d1 = attD[gc + 1];
#pragma unroll
            for (int mi = 0; mi < 2; mi++)
#pragma unroll
                for (int hf = 0; hf < 2; hf++) {
                    psrc[mi][hf] = fmaf(acc[mi][ni][hf * 2], s0, fmaf(acc[mi][ni][hf * 2 + 1], s1, psrc[mi][hf]));
                    pdst[mi][hf] = fmaf(acc[mi][ni][hf * 2], d0, fmaf(acc[mi][ni][hf * 2 + 1], d1, pdst[mi][hf]));
                }
        }
#pragma unroll
        for (int mi = 0; mi < 2; mi++)
#pragma unroll
            for (int hf = 0; hf < 2; hf++) {
#pragma unroll
                for (int off = 1; off < 4; off <<= 1) {
                    psrc[mi][hf] += __shfl_xor_sync(0xffffffffu, psrc[mi][hf], off);
                    pdst[mi][hf] += __shfl_xor_sync(0xffffffffu, pdst[mi][hf], off);
                }
            }
        if ((lane & 3) == 0) {
#pragma unroll
            for (int mi = 0; mi < 2; mi++)
#pragma unroll
                for (int hf = 0; hf < 2; hf++) {
                    int row = crow0 + mi * 16 + hf * 8;
                    if (row < M) {
                        atomicAdd(&aS[(size_t)row * 8 + head], psrc[mi][hf]);
                        if (row < Ndst) atomicAdd(&aD[(size_t)row * 8 + head], pdst[mi][hf]);
                    }
                }
        }
    }

    // ---- store C as fp16 ----
#pragma unroll
    for (int mi = 0; mi < 2; mi++)
#pragma unroll
        for (int hf = 0; hf < 2; hf++) {
            int row = crow0 + mi * 16 + hf * 8;
            if (row < M) {
                __half* cp = C + (size_t)row * Nfull + ccol0;
#pragma unroll
                for (int ni = 0; ni < 8; ni++) {
                    __half2 v = __floats2half2_rn(acc[mi][ni][hf * 2], acc[mi][ni][hf * 2 + 1]);
                    *reinterpret_cast<__half2*>(cp + ni * 8) = v;
                }
            }
        }
}

// ---------------- conversions ----------------
__global__ void conv_f16_kernel(const float* __restrict__ X, __half* __restrict__ Ap,
                                int M, int K)
{
    size_t i = (size_t)blockIdx.x * blockDim.x + threadIdx.x;
    size_t total = (size_t)M * (K >> 2);
    if (i >= total) return;
    float4 v = *reinterpret_cast<const float4*>(X + i * 4);
    *reinterpret_cast<__half2*>(Ap + i * 4)     = __floats2half2_rn(v.x, v.y);
    *reinterpret_cast<__half2*>(Ap + i * 4 + 2) = __floats2half2_rn(v.z, v.w);
}
// W (K x N fp32) -> B (N x K fp16) via 32x32 smem tile transpose (both sides coalesced)
__global__ __launch_bounds__(256) void conv_wt_kernel(
    const float* __restrict__ W, __half* __restrict__ Bp, int K, int N)
{
    __shared__ __half tile[32][33];
    const int tk0 = blockIdx.y * 32;   // K tile base
    const int tn0 = blockIdx.x * 32;   // N tile base
    const int tx = threadIdx.x & 31;   // fast index
    const int ty = threadIdx.x >> 5;   // 0..7
#pragma unroll
    for (int r = 0; r < 4; r++) {
        int k = tk0 + ty + r * 8;
        int n = tn0 + tx;
        if (k < K && n < N)
            tile[ty + r * 8][tx] = __float2half_rn(W[(size_t)k * N + n]);
    }
    __syncthreads();
#pragma unroll
    for (int r = 0; r < 4; r++) {
        int n = tn0 + ty + r * 8;
        int k = tk0 + tx;
        if (n < N && k < K)
            Bp[(size_t)n * K + k] = tile[tx][ty + r * 8];
    }
}

__global__ void zero2_kernel(float* p0, int n0, float* p1, int n1) {
    int i = blockIdx.x * blockDim.x + threadIdx.x;
    if (i < n0) p0[i] = 0.f;
    if (i < n1) p1[i] = 0.f;
}

// ---------------- CSR build (both layers fused) ----------------
__global__ void zero_deg_kernel(int* d1, int n1, int* d2, int n2) {
    int i = blockIdx.x * blockDim.x + threadIdx.x;
    if (i < n1) d1[i] = 0;
    if (i < n2) d2[i] = 0;
}
__global__ void hist2_kernel(const int* __restrict__ dstA, int EA, int* __restrict__ degA,
                             const int* __restrict__ dstB, int EB, int* __restrict__ degB)
{
    int i = blockIdx.x * blockDim.x + threadIdx.x;
    if (i < EA) atomicAdd(&degA[dstA[i]], 1);
    else {
        int j = i - EA;
        if (j < EB) atomicAdd(&degB[dstB[j]], 1);
    }
}
__global__ __launch_bounds__(1024) void scan2_kernel(
    const int* __restrict__ degA, int* __restrict__ rpA, int* __restrict__ curA, int nA,
    const int* __restrict__ degB, int* __restrict__ rpB, int* __restrict__ curB, int nB)
{
    const int* deg = blockIdx.x ? degB : degA;
    int* rowptr = blockIdx.x ? rpB : rpA;
    int* cursor = blockIdx.x ? curB : curA;
    int n = blockIdx.x ? nB : nA;
    __shared__ int sh[1024];
    int t = threadIdx.x;
    int per = (n + 1023) >> 10;
    int lo = t * per;
    int hi = min(lo + per, n);
    int s = 0;
    for (int i = lo; i < hi; i++) s += deg[i];
    sh[t] = s;
    __syncthreads();
    for (int off = 1; off < 1024; off <<= 1) {
        int v = (t >= off) ? sh[t - off] : 0;
        __syncthreads();
        sh[t] += v;
        __syncthreads();
    }
    int run = (t == 0) ? 0 : sh[t - 1];
    for (int i = lo; i < hi; i++) {
        rowptr[i] = run;
        cursor[i] = run;
        run += deg[i];
    }
    if (t == 0) rowptr[n] = sh[1023];
}
__global__ void scatter2_kernel(const int* __restrict__ srcA, const int* __restrict__ dstA, int EA,
                                int* __restrict__ curA, int* __restrict__ colA,
                                const int* __restrict__ srcB, const int* __restrict__ dstB, int EB,
                                int* __restrict__ curB, int* __restrict__ colB)
{
    int i = blockIdx.x * blockDim.x + threadIdx.x;
    if (i < EA) {
        int p = atomicAdd(&curA[dstA[i]], 1);
        colA[p] = srcA[i];
    } else {
        int j = i - EA;
        if (j < EB) {
            int p = atomicAdd(&curB[dstB[j]], 1);
            colB[p] = srcB[j];
        }
    }
}

// ---------------- layer 1: 2-pass softmax + aggregate + bias + ELU -> fp16 a2p ----------------
__global__ __launch_bounds__(128) void agg1_kernel(
    const __half* __restrict__ h1, const float* __restrict__ asrc,
    const float* __restrict__ adst, const int* __restrict__ rowptr,
    const int* __restrict__ col, const float* __restrict__ bias,
    __half* __restrict__ a2p)
{
    const int n = blockIdx.x;
    const int t = threadIdx.x;
    const int warp = t >> 5, lane = t & 31;
    __shared__ float sadst[8], ssr[8];
    __shared__ float red[4][8];
    __shared__ float salpha[16 * 8];
    __shared__ int scol[16];

    const int start = rowptr[n], end = rowptr[n + 1];
    if (t < 8) sadst[t] = adst[n * 8 + t];
    __syncthreads();

    // pass 1: per-head denominator (un-shifted exp; scores are O(1))
    float lsum[8];
#pragma unroll
    for (int h = 0; h < 8; h++) lsum[h] = 0.f;
    for (int j = start + t; j < end; j += 128) {
        const float* ap = asrc + (size_t)col[j] * 8;
#pragma unroll
        for (int h = 0; h < 8; h++) {
            float e = ap[h] + sadst[h];
            e = e > 0.f ? e : NEG_SLOPE * e;
            lsum[h] += __expf(e);
        }
    }
#pragma unroll
    for (int h = 0; h < 8; h++)
#pragma unroll
        for (int off = 16; off > 0; off >>= 1)
            lsum[h] += __shfl_xor_sync(0xffffffffu, lsum[h], off);
    if (lane == 0)
#pragma unroll
        for (int h = 0; h < 8; h++) red[warp][h] = lsum[h];
    __syncthreads();
    if (t < 8) ssr[t] = __frcp_rn(red[0][t] + red[1][t] + red[2][t] + red[3][t]);
    __syncthreads();

    // pass 2: chunked alpha + accumulate
    float acc0 = 0.f, acc1 = 0.f, acc2 = 0.f, acc3 = 0.f;
    const int head = t >> 4;
    const int c4 = t << 2;
    for (int base = start; base < end; base += 16) {
        int cnt = min(16, end - base);
        if (t < cnt) scol[t] = col[base + t];
        if (t < cnt * 8) {
            int j = base + (t >> 3);
            int h = t & 7;
            float e = asrc[(size_t)col[j] * 8 + h] + sadst[h];
            e = e > 0.f ? e : NEG_SLOPE * e;
            salpha[t] = __expf(e) * ssr[h];
        }
        __syncthreads();
        for (int q = 0; q < cnt; q++) {
            int s = scol[q];
            float a = salpha[q * 8 + head];
            const __half2* hp = reinterpret_cast<const __half2*>(h1 + (size_t)s * HC1 + c4);
            float2 v01 = __half22float2(hp[0]);
            float2 v23 = __half22float2(hp[1]);
            acc0 = fmaf(a, v01.x, acc0);
            acc1 = fmaf(a, v01.y, acc1);
            acc2 = fmaf(a, v23.x, acc2);
            acc3 = fmaf(a, v23.y, acc3);
        }
        __syncthreads();
    }
    // bias + ELU -> fp16 store
    float o[4] = {acc0, acc1, acc2, acc3};
#pragma unroll
    for (int i = 0; i < 4; i++) {
        float v = o[i] + bias[c4 + i];
        o[i] = v > 0.f ? v : expm1f(v);
    }
    __half* b = a2p + (size_t)n * HC1 + c4;
    *reinterpret_cast<__half2*>(b)     = __floats2half2_rn(o[0], o[1]);
    *reinterpret_cast<__half2*>(b + 2) = __floats2half2_rn(o[2], o[3]);
}

// ---------------- layer 2: 2-pass softmax + aggregate + head-mean + bias ----------------
__global__ __launch_bounds__(256) void agg2_kernel(
    const __half* __restrict__ h2, const float* __restrict__ asrc,
    const float* __restrict__ adst, const int* __restrict__ rowptr,
    const int* __restrict__ col, const float* __restrict__ bias,
    float* __restrict__ out)
{
    const int n = blockIdx.x;
    const int t = threadIdx.x;
    const int warp = t >> 5, lane = t & 31;
    __shared__ float sadst[8], ssr[8];
    __shared__ float red[8][8];
    __shared__ float salpha[32 * 8];
    __shared__ int scol[32];

    const int start = rowptr[n], end = rowptr[n + 1];
    if (t < 8) sadst[t] = adst[n * 8 + t];
    __syncthreads();

    float lsum[8];
#pragma unroll
    for (int h = 0; h < 8; h++) lsum[h] = 0.f;
    for (int j = start + t; j < end; j += 256) {
        const float* ap = asrc + (size_t)col[j] * 8;
#pragma unroll
        for (int h = 0; h < 8; h++) {
            float e = ap[h] + sadst[h];
            e = e > 0.f ? e : NEG_SLOPE * e;
            lsum[h] += __expf(e);
        }
    }
#pragma unroll
    for (int h = 0; h < 8; h++)
#pragma unroll
        for (int off = 16; off > 0; off >>= 1)
            lsum[h] += __shfl_xor_sync(0xffffffffu, lsum[h], off);
    if (lane == 0)
#pragma unroll
        for (int h = 0; h < 8; h++) red[warp][h] = lsum[h];
    __syncthreads();
    if (t < 8) {
        float s = 0.f;
#pragma unroll
        for (int w = 0; w < 8; w++) s += red[w][t];
        ssr[t] = __frcp_rn(s);
    }
    __syncthreads();

    float acc[8];
#pragma unroll
    for (int h = 0; h < 8; h++) acc[h] = 0.f;
    for (int base = start; base < end; base += 32) {
        int cnt = min(32, end - base);
        if (t < cnt) scol[t] = col[base + t];
        if (t < cnt * 8) {
            int j = base + (t >> 3);
            int h = t & 7;
            float e = asrc[(size_t)col[j] * 8 + h] + sadst[h];
            e = e > 0.f ? e : NEG_SLOPE * e;
            salpha[t] = __expf(e) * ssr[h];
        }
        __syncthreads();
        for (int q = 0; q < cnt; q++) {
            const __half* hp = h2 + (size_t)scol[q] * HC2 + t;
#pragma unroll
            for (int h = 0; h < 8; h++)
                acc[h] = fmaf(salpha[q * 8 + h], __half2float(hp[h * C2]), acc[h]);
        }
        __syncthreads();
    }
    float s = 0.f;
#pragma unroll
    for (int h = 0; h < 8; h++) s += acc[h];
    out[(size_t)n * C2 + t] = 0.125f * s + bias[t];
}

// ---------------- host ----------------
extern "C" void kernel_launch(void* const* d_in, const int* in_sizes, int n_in,
                              void* d_out, int out_size)
{
    const float* x        = (const float*)d_in[0];
    const int*   src1     = (const int*)d_in[1];
    const int*   dst1     = (const int*)d_in[2];
    const int*   src2     = (const int*)d_in[3];
    const int*   dst2     = (const int*)d_in[4];
    const float* W1       = (const float*)d_in[5];
    const float* att_src1 = (const float*)d_in[6];
    const float* att_dst1 = (const float*)d_in[7];
    const float* b1       = (const float*)d_in[8];
    const float* W2       = (const float*)d_in[9];
    const float* att_src2 = (const float*)d_in[10];
    const float* att_dst2 = (const float*)d_in[11];
    const float* b2       = (const float*)d_in[12];
    float* out = (float*)d_out;

    const int E1 = in_sizes[1];
    const int E2 = in_sizes[3];

    float *as1, *ad1, *as2, *ad2;
    int *deg1, *rp1, *cur1, *col1, *deg2, *rp2, *cur2, *col2;
    __half *h1, *h2, *a1p, *b1p, *a2p, *b2p;
    cudaGetSymbolAddress((void**)&h1, g_h1);
    cudaGetSymbolAddress((void**)&h2, g_h2);
    cudaGetSymbolAddress((void**)&as1, g_as1);
    cudaGetSymbolAddress((void**)&ad1, g_ad1);
    cudaGetSymbolAddress((void**)&as2, g_as2);
    cudaGetSymbolAddress((void**)&ad2, g_ad2);
    cudaGetSymbolAddress((void**)&deg1, g_deg1);
    cudaGetSymbolAddress((void**)&rp1, g_rp1);
    cudaGetSymbolAddress((void**)&cur1, g_cur1);
    cudaGetSymbolAddress((void**)&col1, g_col1);
    cudaGetSymbolAddress((void**)&deg2, g_deg2);
    cudaGetSymbolAddress((void**)&rp2, g_rp2);
    cudaGetSymbolAddress((void**)&cur2, g_cur2);
    cudaGetSymbolAddress((void**)&col2, g_col2);
    cudaGetSymbolAddress((void**)&a1p, g_a1p);
    cudaGetSymbolAddress((void**)&b1p, g_b1p);
    cudaGetSymbolAddress((void**)&a2p, g_a2p);
    cudaGetSymbolAddress((void**)&b2p, g_b2p);

    cudaFuncSetAttribute(gemm_mma, cudaFuncAttributeMaxDynamicSharedMemorySize, SMEM_GEMM);

    // ---- layer 1 ----  (GEMM1 stays launch #4 for ncu capture)
    {
        size_t tot = (size_t)N0 * (D / 4);
        conv_f16_kernel<<<(unsigned)((tot + 255) / 256), 256>>>(x, a1p, N0, D);          // 1
    }
    {
        dim3 grid((HC1 + 31) / 32, (D + 31) / 32);
        conv_wt_kernel<<<grid, 256>>>(W1, b1p, D, HC1);                                  // 2
    }
    zero2_kernel<<<(N0 * H1 + 255) / 256, 256>>>(as1, N0 * H1, ad1, N1 * H1);            // 3
    {
        dim3 grid(HC1 / 128, (N0 + 127) / 128);
        gemm_mma<<<grid, 256, SMEM_GEMM>>>(a1p, b1p, h1, N0, HC1, D,                     // 4 (profiled)
                                           att_src1, att_dst1, as1, ad1, C1, N1);
    }

    // ---- fused CSR build (both layers) ----
    zero_deg_kernel<<<(N1 + 255) / 256, 256>>>(deg1, N1, deg2, N2);
    hist2_kernel<<<(E1 + E2 + 255) / 256, 256>>>(dst1, E1, deg1, dst2, E2, deg2);
    scan2_kernel<<<2, 1024>>>(deg1, rp1, cur1, N1, deg2, rp2, cur2, N2);
    scatter2_kernel<<<(E1 + E2 + 255) / 256, 256>>>(src1, dst1, E1, cur1, col1,
                                                    src2, dst2, E2, cur2, col2);

    agg1_kernel<<<N1, 128>>>(h1, as1, ad1, rp1, col1, b1, a2p);

    // ---- layer 2 ----
    {
        dim3 grid((HC2 + 31) / 32, (HC1 + 31) / 32);
        conv_wt_kernel<<<grid, 256>>>(W2, b2p, HC1, HC2);
    }
    zero2_kernel<<<(N1 * H2 + 255) / 256, 256>>>(as2, N1 * H2, ad2, N2 * H2);
    {
        dim3 grid(HC2 / 128, (N1 + 127) / 128);
        gemm_mma<<<grid, 256, SMEM_GEMM>>>(a2p, b2p, h2, N1, HC2, HC1,
                                           att_src2, att_dst2, as2, ad2, C2, N2);
    }

    agg2_kernel<<<N2, 256>>>(h2, as2, ad2, rp2, col2, b2, out);

    (void)n_in; (void)out_size;
}